// round 2
// baseline (speedup 1.0000x reference)
#include <cuda_runtime.h>

#define Bn 64
#define Hn 128
#define Cn 1024
#define Qn 128
#define NT 8           // number of 128-row c tiles (Cn/128)

typedef unsigned long long ull;

// ---- packed f32x2 helpers (two exact fp32 FMAs per instruction) ----
__device__ __forceinline__ ull pk2(float lo, float hi) {
    ull r;
    asm("mov.b64 %0, {%1, %2};" : "=l"(r) : "f"(lo), "f"(hi));
    return r;
}
__device__ __forceinline__ void fma2(ull& d, ull a, ull b) {
    asm("fma.rn.f32x2 %0, %1, %2, %0;" : "+l"(d) : "l"(a), "l"(b));
}
__device__ __forceinline__ float2 upk2(ull v) {
    float2 r;
    asm("mov.b64 {%0, %1}, %2;" : "=f"(r.x), "=f"(r.y) : "l"(v));
    return r;
}

// ---------------- scratch (device globals; no allocation) ----------------
__device__ float g_S[Bn * Cn * Qn];        // raw scores S (33.5 MB)
__device__ float g_cT[Bn * Cn * Hn];       // c transposed: (B, C, H)
__device__ float g_qT[Bn * Qn * Hn];       // q transposed: (B, Q, H)
__device__ float g_rowM[Bn * Cn];
__device__ float g_rowZ[Bn * Cn];
__device__ float g_pM[Bn * NT * Qn];       // per-tile column max partials
__device__ float g_pZ[Bn * NT * Qn];       // per-tile column sumexp partials
__device__ float g_colM[Bn * Qn];
__device__ float g_colZ[Bn * Qn];
__device__ float g_qbp[Bn * NT * Qn * Hn]; // split-K partials of qb
__device__ float g_qb[Bn * Qn * Hn];       // qb = b_att^T @ c^T, normalized

// ---------------- K0: transposes (B,H,L) -> (B,L,H) ----------------
__global__ void ktrans_c(const float* __restrict__ in) {
    __shared__ float t[32][33];
    int b = blockIdx.z;
    int l0 = blockIdx.x * 32, h0 = blockIdx.y * 32;
    int tx = threadIdx.x, ty = threadIdx.y;
#pragma unroll
    for (int i = 0; i < 32; i += 8)
        t[ty + i][tx] = in[((size_t)b * Hn + h0 + ty + i) * Cn + l0 + tx];
    __syncthreads();
#pragma unroll
    for (int i = 0; i < 32; i += 8)
        g_cT[((size_t)b * Cn + l0 + ty + i) * Hn + h0 + tx] = t[tx][ty + i];
}

__global__ void ktrans_q(const float* __restrict__ in) {
    __shared__ float t[32][33];
    int b = blockIdx.z;
    int l0 = blockIdx.x * 32, h0 = blockIdx.y * 32;
    int tx = threadIdx.x, ty = threadIdx.y;
#pragma unroll
    for (int i = 0; i < 32; i += 8)
        t[ty + i][tx] = in[((size_t)b * Hn + h0 + ty + i) * Qn + l0 + tx];
    __syncthreads();
#pragma unroll
    for (int i = 0; i < 32; i += 8)
        g_qT[((size_t)b * Qn + l0 + ty + i) * Hn + h0 + tx] = t[tx][ty + i];
}

// ---------------- K1: scores S + row stats + column partial stats --------
#define K1_SMEM ((16384 * 2 + 5 * 128 + 2048) * 4)

__global__ __launch_bounds__(256, 1) void k1_score(
    const float* __restrict__ c_g, const float* __restrict__ q_g,
    const float* __restrict__ cmask, const float* __restrict__ qmask,
    const float* __restrict__ wc, const float* __restrict__ wq,
    const float* __restrict__ wcq, const float* __restrict__ bias)
{
    extern __shared__ float sm[];
    float* As  = sm;             // [h][cc], c tile (later scaled by wcq)
    float* Bs  = As + 16384;     // [h][q],  q tile
    float* s0s = Bs + 16384;
    float* s1s = s0s + 128;
    float* qms = s1s + 128;
    float* cms = qms + 128;
    float* pmc = cms + 128;
    float* red = pmc + 128;      // 16*128

    int b = blockIdx.y, ct = blockIdx.x, c0 = ct * 128;
    int tid = threadIdx.x, tx = tid & 15, ty = tid >> 4;

    for (int i = tid; i < 16384; i += 256) {
        int h = i >> 7, x = i & 127;
        As[i] = c_g[((size_t)b * Hn + h) * Cn + c0 + x];
        Bs[i] = q_g[((size_t)b * Hn + h) * Qn + x];
    }
    if (tid < 128) { qms[tid] = qmask[b * Qn + tid]; cms[tid] = cmask[b * Cn + c0 + tid]; }
    __syncthreads();

    if (tid < 128) {
        float a = 0.f;
#pragma unroll 8
        for (int h = 0; h < 128; h++) a += As[h * 128 + tid] * wc[h];
        s0s[tid] = a;
    } else {
        int qq = tid - 128; float a = 0.f;
#pragma unroll 8
        for (int h = 0; h < 128; h++) a += Bs[h * 128 + qq] * wq[h];
        s1s[qq] = a;
    }
    __syncthreads();
    for (int i = tid; i < 16384; i += 256) As[i] *= wcq[i >> 7];
    __syncthreads();

    ull acc[8][4];
#pragma unroll
    for (int i = 0; i < 8; i++)
#pragma unroll
        for (int j = 0; j < 4; j++) acc[i][j] = 0ull;

#pragma unroll 2
    for (int k = 0; k < 128; k++) {
        float4 a0 = *(const float4*)&As[k * 128 + ty * 8];
        float4 a1 = *(const float4*)&As[k * 128 + ty * 8 + 4];
        float4 b0 = *(const float4*)&Bs[k * 128 + tx * 8];
        float4 b1 = *(const float4*)&Bs[k * 128 + tx * 8 + 4];
        ull B2[4] = {pk2(b0.x, b0.y), pk2(b0.z, b0.w), pk2(b1.x, b1.y), pk2(b1.z, b1.w)};
        float af[8] = {a0.x, a0.y, a0.z, a0.w, a1.x, a1.y, a1.z, a1.w};
#pragma unroll
        for (int i = 0; i < 8; i++) {
            ull A2 = pk2(af[i], af[i]);
            fma2(acc[i][0], A2, B2[0]);
            fma2(acc[i][1], A2, B2[1]);
            fma2(acc[i][2], A2, B2[2]);
            fma2(acc[i][3], A2, B2[3]);
        }
    }

    float accf[8][8];
#pragma unroll
    for (int i = 0; i < 8; i++)
#pragma unroll
        for (int j = 0; j < 4; j++) {
            float2 v = upk2(acc[i][j]);
            accf[i][2 * j] = v.x; accf[i][2 * j + 1] = v.y;
        }

    float bs0 = bias[0];
#pragma unroll
    for (int i = 0; i < 8; i++) {
        float s0v = s0s[ty * 8 + i];
#pragma unroll
        for (int j = 0; j < 8; j++) accf[i][j] += s0v + s1s[tx * 8 + j] + bs0;
    }

    // write raw S
#pragma unroll
    for (int i = 0; i < 8; i++) {
        size_t off = ((size_t)b * Cn + c0 + ty * 8 + i) * Qn + tx * 8;
        *(float4*)&g_S[off]     = make_float4(accf[i][0], accf[i][1], accf[i][2], accf[i][3]);
        *(float4*)&g_S[off + 4] = make_float4(accf[i][4], accf[i][5], accf[i][6], accf[i][7]);
    }

    // row stats (softmax over q, masked by q_mask)
    float qmv[8];
#pragma unroll
    for (int j = 0; j < 8; j++) qmv[j] = qms[tx * 8 + j];
#pragma unroll
    for (int i = 0; i < 8; i++) {
        float m = -1e30f;
#pragma unroll
        for (int j = 0; j < 8; j++) {
            float rv = (qmv[j] > 0.f) ? accf[i][j] : -1e30f;
            m = fmaxf(m, rv);
        }
#pragma unroll
        for (int off = 8; off >= 1; off >>= 1)
            m = fmaxf(m, __shfl_xor_sync(0xffffffffu, m, off));
        float z = 0.f;
#pragma unroll
        for (int j = 0; j < 8; j++)
            z += (qmv[j] > 0.f) ? __expf(accf[i][j] - m) : 0.f;
#pragma unroll
        for (int off = 8; off >= 1; off >>= 1)
            z += __shfl_xor_sync(0xffffffffu, z, off);
        if (tx == 0) {
            g_rowM[b * Cn + c0 + ty * 8 + i] = m;
            g_rowZ[b * Cn + c0 + ty * 8 + i] = z;
        }
    }

    // column partial stats (softmax over c, masked by c_mask)
    float cmv[8];
#pragma unroll
    for (int i = 0; i < 8; i++) cmv[i] = cms[ty * 8 + i];
#pragma unroll
    for (int j = 0; j < 8; j++) {
        float cm = -1e30f;
#pragma unroll
        for (int i = 0; i < 8; i++) {
            float cv = (cmv[i] > 0.f) ? accf[i][j] : -1e30f;
            cm = fmaxf(cm, cv);
        }
        red[ty * 128 + tx * 8 + j] = cm;
    }
    __syncthreads();
    if (tid < 128) {
        float pm = -1e30f;
#pragma unroll
        for (int t = 0; t < 16; t++) pm = fmaxf(pm, red[t * 128 + tid]);
        pmc[tid] = pm;
    }
    __syncthreads();
#pragma unroll
    for (int j = 0; j < 8; j++) {
        float pm = pmc[tx * 8 + j];
        float cz = 0.f;
#pragma unroll
        for (int i = 0; i < 8; i++)
            cz += (cmv[i] > 0.f) ? __expf(accf[i][j] - pm) : 0.f;
        red[ty * 128 + tx * 8 + j] = cz;
    }
    __syncthreads();
    if (tid < 128) {
        float z = 0.f;
#pragma unroll
        for (int t = 0; t < 16; t++) z += red[t * 128 + tid];
        g_pM[(b * NT + blockIdx.x) * Qn + tid] = pmc[tid];
        g_pZ[(b * NT + blockIdx.x) * Qn + tid] = z;
    }
}

// ---------------- K2: combine column partial stats ----------------
__global__ void k2_colstats() {
    int b = blockIdx.x, q = threadIdx.x;
    float m = -3.4e38f;
#pragma unroll
    for (int t = 0; t < NT; t++) m = fmaxf(m, g_pM[(b * NT + t) * Qn + q]);
    float z = 0.f;
#pragma unroll
    for (int t = 0; t < NT; t++)
        z += g_pZ[(b * NT + t) * Qn + q] * __expf(g_pM[(b * NT + t) * Qn + q] - m);
    g_colM[b * Qn + q] = m;
    g_colZ[b * Qn + q] = z;
}

// ---------------- K3: split-K partials of qb = b_att^T @ c^T ----------------
#define K3_SMEM ((16384 * 2 + 256) * 4)

__global__ __launch_bounds__(256, 1) void k3_qbp(const float* __restrict__ cmask)
{
    extern __shared__ float sm[];
    float* Es  = sm;             // [k=c][q]  un-normalized exp
    float* Cs  = Es + 16384;     // [k=c][h]
    float* cMs = Cs + 16384;
    float* cms = cMs + 128;

    int b = blockIdx.y, ct = blockIdx.x, c0 = ct * 128;
    int tid = threadIdx.x, tx = tid & 15, ty = tid >> 4;

    if (tid < 128) { cMs[tid] = g_colM[b * Qn + tid]; cms[tid] = cmask[b * Cn + c0 + tid]; }
    __syncthreads();

    for (int i = tid; i < 16384; i += 256) {
        int k = i >> 7, x = i & 127;
        float s = g_S[((size_t)b * Cn + c0 + k) * Qn + x];
        Es[i] = (cms[k] > 0.f) ? __expf(s - cMs[x]) : 0.f;
        Cs[i] = g_cT[((size_t)b * Cn + c0 + k) * Hn + x];
    }
    __syncthreads();

    ull acc[8][4];
#pragma unroll
    for (int i = 0; i < 8; i++)
#pragma unroll
        for (int j = 0; j < 4; j++) acc[i][j] = 0ull;

#pragma unroll 2
    for (int k = 0; k < 128; k++) {
        float4 a0 = *(const float4*)&Es[k * 128 + ty * 8];
        float4 a1 = *(const float4*)&Es[k * 128 + ty * 8 + 4];
        float4 b0 = *(const float4*)&Cs[k * 128 + tx * 8];
        float4 b1 = *(const float4*)&Cs[k * 128 + tx * 8 + 4];
        ull B2[4] = {pk2(b0.x, b0.y), pk2(b0.z, b0.w), pk2(b1.x, b1.y), pk2(b1.z, b1.w)};
        float af[8] = {a0.x, a0.y, a0.z, a0.w, a1.x, a1.y, a1.z, a1.w};
#pragma unroll
        for (int i = 0; i < 8; i++) {
            ull A2 = pk2(af[i], af[i]);
            fma2(acc[i][0], A2, B2[0]);
            fma2(acc[i][1], A2, B2[1]);
            fma2(acc[i][2], A2, B2[2]);
            fma2(acc[i][3], A2, B2[3]);
        }
    }

#pragma unroll
    for (int i = 0; i < 8; i++) {
        float2 v0 = upk2(acc[i][0]), v1 = upk2(acc[i][1]);
        float2 v2 = upk2(acc[i][2]), v3 = upk2(acc[i][3]);
        size_t off = ((size_t)(b * NT + ct) * Qn + ty * 8 + i) * Hn + tx * 8;
        *(float4*)&g_qbp[off]     = make_float4(v0.x, v0.y, v1.x, v1.y);
        *(float4*)&g_qbp[off + 4] = make_float4(v2.x, v2.y, v3.x, v3.y);
    }
}

// ---------------- K3b: combine split-K partials, normalize by colZ ----------
__global__ void k3b_combine() {
    int idx = blockIdx.x * 256 + threadIdx.x;   // < Bn*Qn*Hn
    int b = idx >> 14;
    int rem = idx & 16383;
    int q = rem >> 7;
    float s = 0.f;
#pragma unroll
    for (int t = 0; t < NT; t++) s += g_qbp[(size_t)(b * NT + t) * 16384 + rem];
    float z = g_colZ[b * Qn + q];
    g_qb[idx] = (z > 0.f) ? s / z : 0.f;
}

// ---------------- K4: a = A@q^T, bb = A@qb, assemble output ----------------
// Es kept in natural [c][k] layout -> A fragment loads are vector LDS.64 over k.
#define K4_SMEM ((16384 * 3 + 256) * 4)

__global__ __launch_bounds__(256, 1) void k4_out(
    const float* __restrict__ c_g, const float* __restrict__ qmask,
    float* __restrict__ out)
{
    extern __shared__ float sm[];
    float* Es  = sm;             // [cr][k] row-major exp tile
    float* Qs  = Es + 16384;     // [k][h]
    float* QBs = Qs + 16384;     // [k][h]
    float* rms = QBs + 16384;
    float* qms = rms + 128;

    int b = blockIdx.y, ct = blockIdx.x, c0 = ct * 128;
    int tid = threadIdx.x, tx = tid & 15, ty = tid >> 4;

    if (tid < 128) { rms[tid] = g_rowM[b * Cn + c0 + tid]; qms[tid] = qmask[b * Qn + tid]; }
    __syncthreads();

    for (int i = tid; i < 16384; i += 256) {
        int r = i >> 7, x = i & 127;
        float s = g_S[((size_t)b * Cn + c0 + r) * Qn + x];
        Es[i] = (qms[x] > 0.f) ? __expf(s - rms[r]) : 0.f;
        Qs[i]  = g_qT[((size_t)b * Qn + r) * Hn + x];
        QBs[i] = g_qb[((size_t)b * Qn + r) * Hn + x];
    }
    __syncthreads();

    ull aa[8][4], ab[8][4];
#pragma unroll
    for (int i = 0; i < 8; i++)
#pragma unroll
        for (int j = 0; j < 4; j++) { aa[i][j] = 0ull; ab[i][j] = 0ull; }

    int cr0 = ty * 8;
    for (int k0 = 0; k0 < 128; k0 += 2) {
        float2 av[8];
#pragma unroll
        for (int i = 0; i < 8; i++)
            av[i] = *(const float2*)&Es[(cr0 + i) * 128 + k0];
#pragma unroll
        for (int kk = 0; kk < 2; kk++) {
            int k = k0 + kk;
            float4 q0 = *(const float4*)&Qs[k * 128 + tx * 8];
            float4 q1 = *(const float4*)&Qs[k * 128 + tx * 8 + 4];
            float4 p0 = *(const float4*)&QBs[k * 128 + tx * 8];
            float4 p1 = *(const float4*)&QBs[k * 128 + tx * 8 + 4];
            ull BQ[4] = {pk2(q0.x, q0.y), pk2(q0.z, q0.w), pk2(q1.x, q1.y), pk2(q1.z, q1.w)};
            ull BP[4] = {pk2(p0.x, p0.y), pk2(p0.z, p0.w), pk2(p1.x, p1.y), pk2(p1.z, p1.w)};
#pragma unroll
            for (int i = 0; i < 8; i++) {
                float a = kk ? av[i].y : av[i].x;
                ull A2 = pk2(a, a);
                fma2(aa[i][0], A2, BQ[0]);
                fma2(aa[i][1], A2, BQ[1]);
                fma2(aa[i][2], A2, BQ[2]);
                fma2(aa[i][3], A2, BQ[3]);
                fma2(ab[i][0], A2, BP[0]);
                fma2(ab[i][1], A2, BP[1]);
                fma2(ab[i][2], A2, BP[2]);
                fma2(ab[i][3], A2, BP[3]);
            }
        }
    }

    float rz[8];
#pragma unroll
    for (int i = 0; i < 8; i++) {
        float z = g_rowZ[b * Cn + c0 + cr0 + i];
        rz[i] = (z > 0.f) ? 1.f / z : 0.f;
    }

    __syncthreads();   // done reading Qs/QBs; reuse as staging
    float* StA = Qs;
    float* StB = QBs;
#pragma unroll
    for (int i = 0; i < 8; i++) {
        int cr = cr0 + i;
#pragma unroll
        for (int j = 0; j < 4; j++) {
            float2 va = upk2(aa[i][j]);
            float2 vb = upk2(ab[i][j]);
            int h0 = tx * 8 + 2 * j;
            StA[cr * 128 + ((h0 ^ cr) & 127)]       = va.x * rz[i];
            StA[cr * 128 + (((h0 + 1) ^ cr) & 127)] = va.y * rz[i];
            StB[cr * 128 + ((h0 ^ cr) & 127)]       = vb.x * rz[i];
            StB[cr * 128 + (((h0 + 1) ^ cr) & 127)] = vb.y * rz[i];
        }
    }
    __syncthreads();

    const size_t HC = (size_t)Hn * Cn;
    for (int i = tid; i < 16384; i += 256) {
        int h = i >> 7, cc = i & 127;
        float a  = StA[cc * 128 + ((h ^ cc) & 127)];
        float bb = StB[cc * 128 + ((h ^ cc) & 127)];
        float cv = c_g[((size_t)b * Hn + h) * Cn + c0 + cc];
        size_t o = (size_t)b * 4 * HC + (size_t)h * Cn + c0 + cc;
        out[o]          = cv;
        out[o + HC]     = a;
        out[o + 2 * HC] = cv * a;
        out[o + 3 * HC] = cv * bb;
    }
}

// ---------------- launch ----------------
extern "C" void kernel_launch(void* const* d_in, const int* in_sizes, int n_in,
                              void* d_out, int out_size)
{
    const float* c     = (const float*)d_in[0];
    const float* q     = (const float*)d_in[1];
    const float* cmask = (const float*)d_in[2];
    const float* qmask = (const float*)d_in[3];
    const float* wc    = (const float*)d_in[4];
    const float* wq    = (const float*)d_in[5];
    const float* wcq   = (const float*)d_in[6];
    const float* bias  = (const float*)d_in[7];
    float* out = (float*)d_out;

    cudaFuncSetAttribute(k1_score, cudaFuncAttributeMaxDynamicSharedMemorySize, K1_SMEM);
    cudaFuncSetAttribute(k3_qbp,   cudaFuncAttributeMaxDynamicSharedMemorySize, K3_SMEM);
    cudaFuncSetAttribute(k4_out,   cudaFuncAttributeMaxDynamicSharedMemorySize, K4_SMEM);

    ktrans_c<<<dim3(Cn / 32, Hn / 32, Bn), dim3(32, 8)>>>(c);
    ktrans_q<<<dim3(Qn / 32, Hn / 32, Bn), dim3(32, 8)>>>(q);
    k1_score<<<dim3(NT, Bn), 256, K1_SMEM>>>(c, q, cmask, qmask, wc, wq, wcq, bias);
    k2_colstats<<<Bn, Qn>>>();
    k3_qbp<<<dim3(NT, Bn), 256, K3_SMEM>>>(cmask);
    k3b_combine<<<(Bn * Qn * Hn) / 256, 256>>>();
    k4_out<<<dim3(NT, Bn), 256, K4_SMEM>>>(c, qmask, out);
}

// round 3
// speedup vs baseline: 1.4584x; 1.4584x over previous
#include <cuda_runtime.h>

#define Bn 64
#define Hn 128
#define Cn 1024
#define Qn 128
#define NT 8
#define TS 128

typedef unsigned long long ull;

__device__ __forceinline__ void fma2(ull& d, ull a, ull b) {
    asm("fma.rn.f32x2 %0, %1, %2, %0;" : "+l"(d) : "l"(a), "l"(b));
}
__device__ __forceinline__ float2 upk2(ull v) {
    float2 r;
    asm("mov.b64 {%0, %1}, %2;" : "=f"(r.x), "=f"(r.y) : "l"(v));
    return r;
}
__device__ __forceinline__ float mrg(ull v) { float2 t = upk2(v); return t.x + t.y; }

// swizzled K-minor tile store of a float4 (two float2 halves)
__device__ __forceinline__ void store4(float* T, int row, int k4, float4 v) {
    int s = ((row >> 3) & 15) << 1;
    int x0 = row * TS + (k4 ^ s);
    int x1 = row * TS + ((k4 + 2) ^ s);
    *(float2*)&T[x0] = make_float2(v.x, v.y);
    *(float2*)&T[x1] = make_float2(v.z, v.w);
}

// ---------------- scratch ----------------
__device__ float g_S [Bn * Cn * Qn];    // S  [b][c][q]
__device__ float g_St[Bn * Qn * Cn];    // S^T[b][q][c]
__device__ float g_cT[Bn * Cn * Hn];    // c^T[b][c][h]
__device__ float g_qT[Bn * Qn * Hn];    // q^T[b][q][h]
__device__ float g_rowM[Bn * Cn];
__device__ float g_rowZ[Bn * Cn];
__device__ float g_pM[Bn * NT * Qn];
__device__ float g_pZ[Bn * NT * Qn];
__device__ float g_colM[Bn * Qn];
__device__ float g_colZ[Bn * Qn];
__device__ float g_qbp[Bn * NT * Hn * Qn];  // split-K partials of qb^T [h][q]
__device__ float g_qbT[Bn * Hn * Qn];       // qb^T [b][h][q]

// ---------------- K0: transposes ----------------
__global__ void ktrans_c(const float* __restrict__ in) {
    __shared__ float t[32][33];
    int b = blockIdx.z, l0 = blockIdx.x * 32, h0 = blockIdx.y * 32;
    int tx = threadIdx.x, ty = threadIdx.y;
#pragma unroll
    for (int i = 0; i < 32; i += 8)
        t[ty + i][tx] = in[((size_t)b * Hn + h0 + ty + i) * Cn + l0 + tx];
    __syncthreads();
#pragma unroll
    for (int i = 0; i < 32; i += 8)
        g_cT[((size_t)b * Cn + l0 + ty + i) * Hn + h0 + tx] = t[tx][ty + i];
}
__global__ void ktrans_q(const float* __restrict__ in) {
    __shared__ float t[32][33];
    int b = blockIdx.z, l0 = blockIdx.x * 32, h0 = blockIdx.y * 32;
    int tx = threadIdx.x, ty = threadIdx.y;
#pragma unroll
    for (int i = 0; i < 32; i += 8)
        t[ty + i][tx] = in[((size_t)b * Hn + h0 + ty + i) * Qn + l0 + tx];
    __syncthreads();
#pragma unroll
    for (int i = 0; i < 32; i += 8)
        g_qT[((size_t)b * Qn + l0 + ty + i) * Hn + h0 + tx] = t[tx][ty + i];
}

// ---------------- K1: S + S^T + row stats + col partial stats ----------------
#define K1_SMEM ((16384 * 2 + 5 * 128 + 2048) * 4)

__global__ __launch_bounds__(512, 1) void k1_score(
    const float* __restrict__ q_g,
    const float* __restrict__ cmask, const float* __restrict__ qmask,
    const float* __restrict__ wc, const float* __restrict__ wq,
    const float* __restrict__ wcq, const float* __restrict__ bias)
{
    extern __shared__ float sm[];
    float* As  = sm;             // c tile [cc][h] swizzled (unscaled)
    float* Bs  = As + 16384;     // q tile [q][h] swizzled, scaled by wcq[h]
    float* s0s = Bs + 16384;
    float* s1s = s0s + 128;
    float* qms = s1s + 128;
    float* cms = qms + 128;
    float* pmc = cms + 128;
    float* red = pmc + 128;      // 16*128

    int b = blockIdx.y, ct = blockIdx.x, c0 = ct * 128;
    int tid = threadIdx.x, tx = tid & 31, ty = tid >> 5;

    for (int i = tid; i < 4096; i += 512) {
        int row = i >> 5, k4 = (i & 31) << 2;
        float4 vc = *(const float4*)&g_cT[((size_t)b * Cn + c0 + row) * Hn + k4];
        store4(As, row, k4, vc);
        float4 vq = *(const float4*)&g_qT[((size_t)b * Qn + row) * Hn + k4];
        float4 w  = *(const float4*)&wcq[k4];
        vq.x *= w.x; vq.y *= w.y; vq.z *= w.z; vq.w *= w.w;
        store4(Bs, row, k4, vq);
    }
    __syncthreads();

    if (tid < 128) {
        float a = 0.f;
        int s = ((tid >> 3) & 15) << 1;
#pragma unroll 8
        for (int h = 0; h < 128; h++) a += As[tid * TS + (h ^ s)] * wc[h];
        s0s[tid] = a;
    } else if (tid < 256) {
        int qq = tid - 128; float a = 0.f;
#pragma unroll 8
        for (int h = 0; h < 128; h++) a += g_qT[((size_t)b * Qn + qq) * Hn + h] * wq[h];
        s1s[qq] = a;
    } else if (tid < 384) {
        qms[tid - 256] = qmask[b * Qn + tid - 256];
    } else {
        cms[tid - 384] = cmask[b * Cn + c0 + tid - 384];
    }
    __syncthreads();

    // mainloop: acc2[i][j], K-paired
    ull acc[8][4];
#pragma unroll
    for (int i = 0; i < 8; i++)
#pragma unroll
        for (int j = 0; j < 4; j++) acc[i][j] = 0ull;

    int aoff = ty * 8 * TS, boff = tx * 4 * TS;
    int sA = (ty & 15) << 1, sB = tx & ~1;
#pragma unroll 1
    for (int kp = 0; kp < 64; kp++) {
        int ka = aoff + ((2 * kp) ^ sA);
        int kb = boff + ((2 * kp) ^ sB);
        ull A2[8], B2[4];
#pragma unroll
        for (int i = 0; i < 8; i++) A2[i] = *(const ull*)&As[ka + i * TS];
#pragma unroll
        for (int j = 0; j < 4; j++) B2[j] = *(const ull*)&Bs[kb + j * TS];
#pragma unroll
        for (int i = 0; i < 8; i++)
#pragma unroll
            for (int j = 0; j < 4; j++) fma2(acc[i][j], A2[i], B2[j]);
    }

    float accf[8][4];
    float bs0 = bias[0];
#pragma unroll
    for (int i = 0; i < 8; i++) {
        float s0v = s0s[ty * 8 + i];
#pragma unroll
        for (int j = 0; j < 4; j++)
            accf[i][j] = mrg(acc[i][j]) + s0v + s1s[tx * 4 + j] + bs0;
    }

    // write S [c][q]
#pragma unroll
    for (int i = 0; i < 8; i++) {
        size_t off = ((size_t)b * Cn + c0 + ty * 8 + i) * Qn + tx * 4;
        *(float4*)&g_S[off] = make_float4(accf[i][0], accf[i][1], accf[i][2], accf[i][3]);
    }

    // row stats (softmax over q)
    float qmv[4];
#pragma unroll
    for (int j = 0; j < 4; j++) qmv[j] = qms[tx * 4 + j];
#pragma unroll
    for (int i = 0; i < 8; i++) {
        float m = -1e30f;
#pragma unroll
        for (int j = 0; j < 4; j++)
            m = fmaxf(m, (qmv[j] > 0.f) ? accf[i][j] : -1e30f);
#pragma unroll
        for (int off = 16; off >= 1; off >>= 1)
            m = fmaxf(m, __shfl_xor_sync(0xffffffffu, m, off));
        float z = 0.f;
#pragma unroll
        for (int j = 0; j < 4; j++)
            z += (qmv[j] > 0.f) ? __expf(accf[i][j] - m) : 0.f;
#pragma unroll
        for (int off = 16; off >= 1; off >>= 1)
            z += __shfl_xor_sync(0xffffffffu, z, off);
        if (tx == 0) {
            g_rowM[b * Cn + c0 + ty * 8 + i] = m;
            g_rowZ[b * Cn + c0 + ty * 8 + i] = z;
        }
    }

    // column partial stats (softmax over c)
    float cmv[8];
#pragma unroll
    for (int i = 0; i < 8; i++) cmv[i] = cms[ty * 8 + i];
#pragma unroll
    for (int j = 0; j < 4; j++) {
        float cm = -1e30f;
#pragma unroll
        for (int i = 0; i < 8; i++)
            cm = fmaxf(cm, (cmv[i] > 0.f) ? accf[i][j] : -1e30f);
        red[ty * 128 + tx * 4 + j] = cm;
    }
    __syncthreads();
    if (tid < 128) {
        float pm = -1e30f;
#pragma unroll
        for (int t = 0; t < 16; t++) pm = fmaxf(pm, red[t * 128 + tid]);
        pmc[tid] = pm;
    }
    __syncthreads();
#pragma unroll
    for (int j = 0; j < 4; j++) {
        float pm = pmc[tx * 4 + j];
        float cz = 0.f;
#pragma unroll
        for (int i = 0; i < 8; i++)
            cz += (cmv[i] > 0.f) ? __expf(accf[i][j] - pm) : 0.f;
        red[ty * 128 + tx * 4 + j] = cz;
    }
    __syncthreads();
    if (tid < 128) {
        float z = 0.f;
#pragma unroll
        for (int t = 0; t < 16; t++) z += red[t * 128 + tid];
        g_pM[(b * NT + ct) * Qn + tid] = pmc[tid];
        g_pZ[(b * NT + ct) * Qn + tid] = z;
    }
    __syncthreads();

    // stage S^T [q][cc] into As, then coalesced global write
#pragma unroll
    for (int i = 0; i < 8; i++) {
        int cc = ty * 8 + i;
#pragma unroll
        for (int j = 0; j < 4; j++) {
            int qq = tx * 4 + j;
            As[qq * 128 + ((cc ^ qq) & 127)] = accf[i][j];
        }
    }
    __syncthreads();
    for (int i = tid; i < 16384; i += 512) {
        int qq = i >> 7, cc = i & 127;
        g_St[((size_t)b * Qn + qq) * Cn + c0 + cc] = As[qq * 128 + ((cc ^ qq) & 127)];
    }
}

// ---------------- K2: combine column partial stats ----------------
__global__ void k2_colstats() {
    int b = blockIdx.x, q = threadIdx.x;
    float m = -3.4e38f;
#pragma unroll
    for (int t = 0; t < NT; t++) m = fmaxf(m, g_pM[(b * NT + t) * Qn + q]);
    float z = 0.f;
#pragma unroll
    for (int t = 0; t < NT; t++)
        z += g_pZ[(b * NT + t) * Qn + q] * __expf(g_pM[(b * NT + t) * Qn + q] - m);
    g_colM[b * Qn + q] = m;
    g_colZ[b * Qn + q] = z;
}

// ---------------- K3: qb^T partials = c @ E2^T ----------------
#define K3_SMEM ((16384 * 2 + 256) * 4)

__global__ __launch_bounds__(512, 1) void k3_qbp(
    const float* __restrict__ c_g, const float* __restrict__ cmask)
{
    extern __shared__ float sm[];
    float* Cs  = sm;             // [h][c] swizzled
    float* Es  = Cs + 16384;     // [q][c] swizzled: exp(St - colM[q]) masked by cmask[c]
    float* cMs = Es + 16384;
    float* cms = cMs + 128;

    int b = blockIdx.y, ct = blockIdx.x, c0 = ct * 128;
    int tid = threadIdx.x, tx = tid & 31, ty = tid >> 5;

    if (tid < 128) cMs[tid] = g_colM[b * Qn + tid];
    else if (tid < 256) cms[tid - 128] = cmask[b * Cn + c0 + tid - 128];
    __syncthreads();

    for (int i = tid; i < 4096; i += 512) {
        int row = i >> 5, k4 = (i & 31) << 2;
        float4 vc = *(const float4*)&c_g[((size_t)b * Hn + row) * Cn + c0 + k4];
        store4(Cs, row, k4, vc);
        float4 s4 = *(const float4*)&g_St[((size_t)b * Qn + row) * Cn + c0 + k4];
        float cM = cMs[row];
        float4 e;
        e.x = (cms[k4 + 0] > 0.f) ? __expf(s4.x - cM) : 0.f;
        e.y = (cms[k4 + 1] > 0.f) ? __expf(s4.y - cM) : 0.f;
        e.z = (cms[k4 + 2] > 0.f) ? __expf(s4.z - cM) : 0.f;
        e.w = (cms[k4 + 3] > 0.f) ? __expf(s4.w - cM) : 0.f;
        store4(Es, row, k4, e);
    }
    __syncthreads();

    ull acc[8][4];
#pragma unroll
    for (int i = 0; i < 8; i++)
#pragma unroll
        for (int j = 0; j < 4; j++) acc[i][j] = 0ull;

    int aoff = ty * 8 * TS, boff = tx * 4 * TS;
    int sA = (ty & 15) << 1, sB = tx & ~1;
#pragma unroll 1
    for (int kp = 0; kp < 64; kp++) {
        int ka = aoff + ((2 * kp) ^ sA);
        int kb = boff + ((2 * kp) ^ sB);
        ull A2[8], B2[4];
#pragma unroll
        for (int i = 0; i < 8; i++) A2[i] = *(const ull*)&Cs[ka + i * TS];
#pragma unroll
        for (int j = 0; j < 4; j++) B2[j] = *(const ull*)&Es[kb + j * TS];
#pragma unroll
        for (int i = 0; i < 8; i++)
#pragma unroll
            for (int j = 0; j < 4; j++) fma2(acc[i][j], A2[i], B2[j]);
    }

#pragma unroll
    for (int i = 0; i < 8; i++) {
        int h = ty * 8 + i;
        size_t off = ((size_t)(b * NT + ct) * Hn + h) * Qn + tx * 4;
        *(float4*)&g_qbp[off] = make_float4(mrg(acc[i][0]), mrg(acc[i][1]),
                                            mrg(acc[i][2]), mrg(acc[i][3]));
    }
}

// ---------------- K3b: combine split-K partials ----------------
__global__ void k3b_combine() {
    int idx = blockIdx.x * 256 + threadIdx.x;
    int b = idx >> 14, rem = idx & 16383, q = idx & 127;
    float s = 0.f;
#pragma unroll
    for (int t = 0; t < NT; t++) s += g_qbp[(size_t)(b * NT + t) * 16384 + rem];
    float z = g_colZ[b * Qn + q];
    g_qbT[idx] = (z > 0.f) ? s / z : 0.f;
}

// ---------------- K4: a = E@q^T, bb = E@qb; assemble ----------------
#define K4_SMEM ((16384 * 3 + 3 * 128) * 4)

__global__ __launch_bounds__(512, 1) void k4_out(
    const float* __restrict__ c_g, const float* __restrict__ q_g,
    const float* __restrict__ qmask, float* __restrict__ out)
{
    extern __shared__ float sm[];
    float* Es   = sm;            // [cr][q] swizzled
    float* Bq   = Es + 16384;    // [h][q]  swizzled (later StA staging)
    float* Bqb  = Bq + 16384;    // [h][q]  swizzled (later StB staging)
    float* rmss = Bqb + 16384;
    float* qmss = rmss + 128;
    float* rzs  = qmss + 128;

    int b = blockIdx.y, ct = blockIdx.x, c0 = ct * 128;
    int tid = threadIdx.x, tx = tid & 31, ty = tid >> 5;

    if (tid < 128) rmss[tid] = g_rowM[b * Cn + c0 + tid];
    else if (tid < 256) qmss[tid - 128] = qmask[b * Qn + tid - 128];
    else if (tid < 384) {
        float z = g_rowZ[b * Cn + c0 + tid - 256];
        rzs[tid - 256] = (z > 0.f) ? 1.f / z : 0.f;
    }
    __syncthreads();

    for (int i = tid; i < 4096; i += 512) {
        int row = i >> 5, k4 = (i & 31) << 2;
        float4 s4 = *(const float4*)&g_S[((size_t)b * Cn + c0 + row) * Qn + k4];
        float rm = rmss[row];
        float4 e;
        e.x = (qmss[k4 + 0] > 0.f) ? __expf(s4.x - rm) : 0.f;
        e.y = (qmss[k4 + 1] > 0.f) ? __expf(s4.y - rm) : 0.f;
        e.z = (qmss[k4 + 2] > 0.f) ? __expf(s4.z - rm) : 0.f;
        e.w = (qmss[k4 + 3] > 0.f) ? __expf(s4.w - rm) : 0.f;
        store4(Es, row, k4, e);
        float4 vq = *(const float4*)&q_g[((size_t)b * Hn + row) * Qn + k4];
        store4(Bq, row, k4, vq);
        float4 vp = *(const float4*)&g_qbT[((size_t)b * Hn + row) * Qn + k4];
        store4(Bqb, row, k4, vp);
    }
    __syncthreads();

    int aoff = ty * 8 * TS, boff = tx * 4 * TS;
    int sA = (ty & 15) << 1, sB = tx & ~1;
    int cr0 = ty * 8;

    // ---- loop 1: aa = E @ Bq^T ----
    {
        ull aa[8][4];
#pragma unroll
        for (int i = 0; i < 8; i++)
#pragma unroll
            for (int j = 0; j < 4; j++) aa[i][j] = 0ull;
#pragma unroll 1
        for (int kp = 0; kp < 64; kp++) {
            int ka = aoff + ((2 * kp) ^ sA);
            int kb = boff + ((2 * kp) ^ sB);
            ull A2[8], B2[4];
#pragma unroll
            for (int i = 0; i < 8; i++) A2[i] = *(const ull*)&Es[ka + i * TS];
#pragma unroll
            for (int j = 0; j < 4; j++) B2[j] = *(const ull*)&Bq[kb + j * TS];
#pragma unroll
            for (int i = 0; i < 8; i++)
#pragma unroll
                for (int j = 0; j < 4; j++) fma2(aa[i][j], A2[i], B2[j]);
        }
        __syncthreads();      // everyone done reading Bq
#pragma unroll
        for (int i = 0; i < 8; i++) {
            int cr = cr0 + i;
            float rz = rzs[cr];
#pragma unroll
            for (int j = 0; j < 4; j++) {
                int h = tx * 4 + j;
                Bq[cr * 128 + ((h ^ cr) & 127)] = mrg(aa[i][j]) * rz;   // StA
            }
        }
    }

    // ---- loop 2: ab = E @ Bqb^T ----
    {
        ull ab[8][4];
#pragma unroll
        for (int i = 0; i < 8; i++)
#pragma unroll
            for (int j = 0; j < 4; j++) ab[i][j] = 0ull;
#pragma unroll 1
        for (int kp = 0; kp < 64; kp++) {
            int ka = aoff + ((2 * kp) ^ sA);
            int kb = boff + ((2 * kp) ^ sB);
            ull A2[8], B2[4];
#pragma unroll
            for (int i = 0; i < 8; i++) A2[i] = *(const ull*)&Es[ka + i * TS];
#pragma unroll
            for (int j = 0; j < 4; j++) B2[j] = *(const ull*)&Bqb[kb + j * TS];
#pragma unroll
            for (int i = 0; i < 8; i++)
#pragma unroll
                for (int j = 0; j < 4; j++) fma2(ab[i][j], A2[i], B2[j]);
        }
        __syncthreads();      // everyone done reading Bqb / Es
#pragma unroll
        for (int i = 0; i < 8; i++) {
            int cr = cr0 + i;
            float rz = rzs[cr];
#pragma unroll
            for (int j = 0; j < 4; j++) {
                int h = tx * 4 + j;
                Bqb[cr * 128 + ((h ^ cr) & 127)] = mrg(ab[i][j]) * rz;  // StB
            }
        }
    }
    __syncthreads();

    const size_t HC = (size_t)Hn * Cn;
    for (int i = tid; i < 16384; i += 512) {
        int h = i >> 7, cc = i & 127;
        float a  = Bq [cc * 128 + ((h ^ cc) & 127)];
        float bb = Bqb[cc * 128 + ((h ^ cc) & 127)];
        float cv = c_g[((size_t)b * Hn + h) * Cn + c0 + cc];
        size_t o = (size_t)b * 4 * HC + (size_t)h * Cn + c0 + cc;
        out[o]          = cv;
        out[o + HC]     = a;
        out[o + 2 * HC] = cv * a;
        out[o + 3 * HC] = cv * bb;
    }
}

// ---------------- launch ----------------
extern "C" void kernel_launch(void* const* d_in, const int* in_sizes, int n_in,
                              void* d_out, int out_size)
{
    const float* c     = (const float*)d_in[0];
    const float* q     = (const float*)d_in[1];
    const float* cmask = (const float*)d_in[2];
    const float* qmask = (const float*)d_in[3];
    const float* wc    = (const float*)d_in[4];
    const float* wq    = (const float*)d_in[5];
    const float* wcq   = (const float*)d_in[6];
    const float* bias  = (const float*)d_in[7];
    float* out = (float*)d_out;

    cudaFuncSetAttribute(k1_score, cudaFuncAttributeMaxDynamicSharedMemorySize, K1_SMEM);
    cudaFuncSetAttribute(k3_qbp,   cudaFuncAttributeMaxDynamicSharedMemorySize, K3_SMEM);
    cudaFuncSetAttribute(k4_out,   cudaFuncAttributeMaxDynamicSharedMemorySize, K4_SMEM);

    ktrans_c<<<dim3(Cn / 32, Hn / 32, Bn), dim3(32, 8)>>>(c);
    ktrans_q<<<dim3(Qn / 32, Hn / 32, Bn), dim3(32, 8)>>>(q);
    k1_score<<<dim3(NT, Bn), 512, K1_SMEM>>>(q, cmask, qmask, wc, wq, wcq, bias);
    k2_colstats<<<Bn, Qn>>>();
    k3_qbp<<<dim3(NT, Bn), 512, K3_SMEM>>>(c, cmask);
    k3b_combine<<<(Bn * Qn * Hn) / 256, 256>>>();
    k4_out<<<dim3(NT, Bn), 512, K4_SMEM>>>(c, q, qmask, out);
}

// round 5
// speedup vs baseline: 2.2954x; 1.5740x over previous
#include <cuda_runtime.h>
#include <cuda_bf16.h>

#define Bn 64
#define Hn 128
#define Cn 1024
#define Qn 128
#define NT 8

typedef unsigned int u32;

// ---------------- scratch ----------------
__device__ float g_S [Bn * Cn * Qn];
__device__ float g_St[Bn * Qn * Cn];
__device__ float g_cT[Bn * Cn * Hn];
__device__ float g_qT[Bn * Qn * Hn];
__device__ float g_rowM[Bn * Cn];
__device__ float g_rowZ[Bn * Cn];
__device__ float g_colM[Bn * Qn];
__device__ float g_colZ[Bn * Qn];
__device__ float g_qbp[Bn * NT * Hn * Qn];
__device__ float g_qbT[Bn * Hn * Qn];

// ---------------- helpers ----------------
__device__ __forceinline__ u32 smem_u32(const void* p) {
    u32 a;
    asm("{ .reg .u64 t; cvta.to.shared.u64 t, %1; cvt.u32.u64 %0, t; }" : "=r"(a) : "l"(p));
    return a;
}
__device__ __forceinline__ void ldsm4(u32 a, u32* r) {
    asm volatile("ldmatrix.sync.aligned.m8n8.x4.shared.b16 {%0,%1,%2,%3}, [%4];"
        : "=r"(r[0]), "=r"(r[1]), "=r"(r[2]), "=r"(r[3]) : "r"(a));
}
__device__ __forceinline__ void mmabf(float* d, const u32* a, u32 b0, u32 b1) {
    asm volatile("mma.sync.aligned.m16n8k16.row.col.f32.bf16.bf16.f32 "
        "{%0,%1,%2,%3},{%4,%5,%6,%7},{%8,%9},{%0,%1,%2,%3};"
        : "+f"(d[0]), "+f"(d[1]), "+f"(d[2]), "+f"(d[3])
        : "r"(a[0]), "r"(a[1]), "r"(a[2]), "r"(a[3]), "r"(b0), "r"(b1));
}

// split 8 fp32 into bf16 hi + bf16 lo, store 16B at swizzled slot of K-minor tile
// tile row = 128 bf16 = 256B = 16 slots of 16B; slot' = slot ^ (row & 7)
__device__ __forceinline__ void split8(char* hi, char* lo, int r, int slot,
                                       float4 v0, float4 v1)
{
    float f[8] = {v0.x, v0.y, v0.z, v0.w, v1.x, v1.y, v1.z, v1.w};
    u32 H[4], L[4];
#pragma unroll
    for (int j = 0; j < 4; j++) {
        float a = f[2 * j], b = f[2 * j + 1];
        __nv_bfloat16 ha = __float2bfloat16(a), hb = __float2bfloat16(b);
        float fa = __bfloat162float(ha), fb = __bfloat162float(hb);
        __nv_bfloat162 hp; hp.x = ha; hp.y = hb;
        H[j] = *(u32*)&hp;
        __nv_bfloat162 lp = __floats2bfloat162_rn(a - fa, b - fb);
        L[j] = *(u32*)&lp;
    }
    u32 off = (u32)r * 256 + (u32)((slot ^ (r & 7)) << 4);
    *(uint4*)(hi + off) = make_uint4(H[0], H[1], H[2], H[3]);
    *(uint4*)(lo + off) = make_uint4(L[0], L[1], L[2], L[3]);
}

// 128x128x128 warp-tile GEMM: D[m][n] += A[m][k]*B[n][k], bf16 hi/lo x3 emulation.
// 16 warps: warp (mw,nw) computes 32x32. acc[2][4][4] = (m-frag, n-frag, d-regs)
__device__ __forceinline__ void warp_gemm128(u32 ah, u32 al, u32 bh, u32 bl,
                                             int lane, int m0, int n0,
                                             float acc[2][4][4])
{
    int rA = lane & 15, hi16 = lane >> 4;
    int rBl = (lane & 7) + ((lane >> 4) << 3);
    int kh = (lane >> 3) & 1;
    int rowA[2] = {m0 + rA, m0 + 16 + rA};
    int rowB[2] = {n0 + rBl, n0 + 16 + rBl};
#pragma unroll
    for (int ks = 0; ks < 8; ks++) {
        u32 AH[2][4], AL[2][4], BH[2][4], BL[2][4];
#pragma unroll
        for (int f = 0; f < 2; f++) {
            u32 sa = (u32)rowA[f] * 256 + (u32)((((ks << 1) + hi16) ^ (rowA[f] & 7)) << 4);
            ldsm4(ah + sa, AH[f]);
            ldsm4(al + sa, AL[f]);
            u32 sb = (u32)rowB[f] * 256 + (u32)((((ks << 1) + kh) ^ (rowB[f] & 7)) << 4);
            ldsm4(bh + sb, BH[f]);
            ldsm4(bl + sb, BL[f]);
        }
#pragma unroll
        for (int mf = 0; mf < 2; mf++)
#pragma unroll
            for (int nh = 0; nh < 2; nh++)
#pragma unroll
                for (int no = 0; no < 2; no++) {
                    float* d = acc[mf][nh * 2 + no];
                    mmabf(d, AH[mf], BH[nh][2 * no], BH[nh][2 * no + 1]);
                    mmabf(d, AH[mf], BL[nh][2 * no], BL[nh][2 * no + 1]);
                    mmabf(d, AL[mf], BH[nh][2 * no], BH[nh][2 * no + 1]);
                }
    }
}

// ---------------- K0: transposes (B,H,L) -> (B,L,H) ----------------
__global__ void ktrans_c(const float* __restrict__ in) {
    __shared__ float t[32][33];
    int b = blockIdx.z, l0 = blockIdx.x * 32, h0 = blockIdx.y * 32;
    int tx = threadIdx.x, ty = threadIdx.y;
#pragma unroll
    for (int i = 0; i < 32; i += 8)
        t[ty + i][tx] = in[((size_t)b * Hn + h0 + ty + i) * Cn + l0 + tx];
    __syncthreads();
#pragma unroll
    for (int i = 0; i < 32; i += 8)
        g_cT[((size_t)b * Cn + l0 + ty + i) * Hn + h0 + tx] = t[tx][ty + i];
}
__global__ void ktrans_q(const float* __restrict__ in) {
    __shared__ float t[32][33];
    int b = blockIdx.z, l0 = blockIdx.x * 32, h0 = blockIdx.y * 32;
    int tx = threadIdx.x, ty = threadIdx.y;
#pragma unroll
    for (int i = 0; i < 32; i += 8)
        t[ty + i][tx] = in[((size_t)b * Hn + h0 + ty + i) * Qn + l0 + tx];
    __syncthreads();
#pragma unroll
    for (int i = 0; i < 32; i += 8)
        g_qT[((size_t)b * Qn + l0 + ty + i) * Hn + h0 + tx] = t[tx][ty + i];
}

// ---------------- K1: S = c^T·(wcq q)^T + s0 + s1 + bias ----------------
#define K1_SMEM (131072 + 1024)

__global__ __launch_bounds__(512) void k1_score(
    const float* __restrict__ wc, const float* __restrict__ wq,
    const float* __restrict__ wcq, const float* __restrict__ bias)
{
    extern __shared__ __align__(256) char smem[];
    u32 sb = smem_u32(smem);
    float* s0s = (float*)(smem + 131072);
    float* s1s = s0s + 128;
    int tid = threadIdx.x, lane = tid & 31, wid = tid >> 5;
    int b = blockIdx.y, c0 = blockIdx.x * 128;

    for (int i = tid; i < 2048; i += 512) {
        int r = i >> 4, slot = i & 15;
        const float* pa = &g_cT[((size_t)b * Cn + c0 + r) * Hn + slot * 8];
        split8(smem, smem + 32768, r, slot, *(const float4*)pa, *(const float4*)(pa + 4));
        const float* pb = &g_qT[((size_t)b * Qn + r) * Hn + slot * 8];
        float4 v0 = *(const float4*)pb, v1 = *(const float4*)(pb + 4);
        float4 w0 = *(const float4*)&wcq[slot * 8], w1 = *(const float4*)&wcq[slot * 8 + 4];
        v0.x *= w0.x; v0.y *= w0.y; v0.z *= w0.z; v0.w *= w0.w;
        v1.x *= w1.x; v1.y *= w1.y; v1.z *= w1.z; v1.w *= w1.w;
        split8(smem + 65536, smem + 98304, r, slot, v0, v1);
    }
    if (tid < 128) {
        const float* row = &g_cT[((size_t)b * Cn + c0 + tid) * Hn];
        float a = 0.f;
#pragma unroll 8
        for (int h = 0; h < 128; h++) a += row[h] * wc[h];
        s0s[tid] = a + bias[0];
    } else if (tid < 256) {
        int qq = tid - 128;
        const float* row = &g_qT[((size_t)b * Qn + qq) * Hn];
        float a = 0.f;
#pragma unroll 8
        for (int h = 0; h < 128; h++) a += row[h] * wq[h];
        s1s[qq] = a;
    }
    __syncthreads();

    float acc[2][4][4];
#pragma unroll
    for (int i = 0; i < 2; i++)
#pragma unroll
        for (int j = 0; j < 4; j++)
#pragma unroll
            for (int k = 0; k < 4; k++) acc[i][j][k] = 0.f;

    int m0 = (wid >> 2) * 32, n0 = (wid & 3) * 32;
    warp_gemm128(sb, sb + 32768, sb + 65536, sb + 98304, lane, m0, n0, acc);

    int lr = lane >> 2, lc = (lane & 3) * 2;

    // write S (frag layout, float2 stores)
#pragma unroll
    for (int mf = 0; mf < 2; mf++) {
        int r0l = m0 + mf * 16 + lr, r1l = r0l + 8;
        float s0a = s0s[r0l], s0b = s0s[r1l];
#pragma unroll
        for (int nf = 0; nf < 4; nf++) {
            int col = n0 + nf * 8 + lc;
            float d0 = acc[mf][nf][0] + s0a + s1s[col];
            float d1 = acc[mf][nf][1] + s0a + s1s[col + 1];
            float d2 = acc[mf][nf][2] + s0b + s1s[col];
            float d3 = acc[mf][nf][3] + s0b + s1s[col + 1];
            *(float2*)&g_S[((size_t)b * Cn + c0 + r0l) * Qn + col] = make_float2(d0, d1);
            *(float2*)&g_S[((size_t)b * Cn + c0 + r1l) * Qn + col] = make_float2(d2, d3);
        }
    }
    __syncthreads();   // tiles no longer needed; reuse as S^T staging

    float* Sts = (float*)smem;
#pragma unroll
    for (int mf = 0; mf < 2; mf++) {
        int r0l = m0 + mf * 16 + lr, r1l = r0l + 8;
        float s0a = s0s[r0l], s0b = s0s[r1l];
#pragma unroll
        for (int nf = 0; nf < 4; nf++) {
            int col = n0 + nf * 8 + lc;
            Sts[col * 128 + ((r0l ^ col) & 127)]             = acc[mf][nf][0] + s0a + s1s[col];
            Sts[(col + 1) * 128 + ((r0l ^ (col + 1)) & 127)] = acc[mf][nf][1] + s0a + s1s[col + 1];
            Sts[col * 128 + ((r1l ^ col) & 127)]             = acc[mf][nf][2] + s0b + s1s[col];
            Sts[(col + 1) * 128 + ((r1l ^ (col + 1)) & 127)] = acc[mf][nf][3] + s0b + s1s[col + 1];
        }
    }
    __syncthreads();
    for (int i = tid; i < 16384; i += 512) {
        int q = i >> 7, cc = i & 127;
        g_St[((size_t)b * Qn + q) * Cn + c0 + cc] = Sts[(q << 7) + ((cc ^ q) & 127)];
    }
}

// ---------------- row / col softmax stats ----------------
__global__ void kstat_row(const float* __restrict__ qmask) {
    int b = blockIdx.y;
    int w = threadIdx.x >> 5, l = threadIdx.x & 31;
    int c = blockIdx.x * 8 + w;
    float4 qm = *(const float4*)&qmask[b * Qn + l * 4];
    float4 s = *(const float4*)&g_S[((size_t)b * Cn + c) * Qn + l * 4];
    float v0 = (qm.x > 0.f) ? s.x : -1e30f;
    float v1 = (qm.y > 0.f) ? s.y : -1e30f;
    float v2 = (qm.z > 0.f) ? s.z : -1e30f;
    float v3 = (qm.w > 0.f) ? s.w : -1e30f;
    float m = fmaxf(fmaxf(v0, v1), fmaxf(v2, v3));
#pragma unroll
    for (int o = 16; o >= 1; o >>= 1) m = fmaxf(m, __shfl_xor_sync(~0u, m, o));
    float z = ((v0 > -1e29f) ? __expf(v0 - m) : 0.f) + ((v1 > -1e29f) ? __expf(v1 - m) : 0.f)
            + ((v2 > -1e29f) ? __expf(v2 - m) : 0.f) + ((v3 > -1e29f) ? __expf(v3 - m) : 0.f);
#pragma unroll
    for (int o = 16; o >= 1; o >>= 1) z += __shfl_xor_sync(~0u, z, o);
    if (l == 0) { g_rowM[b * Cn + c] = m; g_rowZ[b * Cn + c] = z; }
}

__global__ void kstat_col(const float* __restrict__ cmask) {
    int b = blockIdx.y;
    int w = threadIdx.x >> 5, l = threadIdx.x & 31;
    int q = blockIdx.x * 8 + w;
    float v[32];
    float m = -1e30f;
#pragma unroll
    for (int it = 0; it < 8; it++) {
        int col = it * 128 + l * 4;
        float4 s = *(const float4*)&g_St[((size_t)b * Qn + q) * Cn + col];
        float4 cm = *(const float4*)&cmask[b * Cn + col];
        v[it * 4 + 0] = (cm.x > 0.f) ? s.x : -1e30f;
        v[it * 4 + 1] = (cm.y > 0.f) ? s.y : -1e30f;
        v[it * 4 + 2] = (cm.z > 0.f) ? s.z : -1e30f;
        v[it * 4 + 3] = (cm.w > 0.f) ? s.w : -1e30f;
#pragma unroll
        for (int j = 0; j < 4; j++) m = fmaxf(m, v[it * 4 + j]);
    }
#pragma unroll
    for (int o = 16; o >= 1; o >>= 1) m = fmaxf(m, __shfl_xor_sync(~0u, m, o));
    float z = 0.f;
#pragma unroll
    for (int t = 0; t < 32; t++) z += (v[t] > -1e29f) ? __expf(v[t] - m) : 0.f;
#pragma unroll
    for (int o = 16; o >= 1; o >>= 1) z += __shfl_xor_sync(~0u, z, o);
    if (l == 0) { g_colM[b * Qn + q] = m; g_colZ[b * Qn + q] = z; }
}

// ---------------- K3: qb^T partials = c · E2^T ----------------
#define K3_SMEM (131072 + 1024)

__global__ __launch_bounds__(512) void k3_qbp(
    const float* __restrict__ c_g, const float* __restrict__ cmask)
{
    extern __shared__ __align__(256) char smem[];
    u32 sb = smem_u32(smem);
    float* cMs = (float*)(smem + 131072);
    float* cms = cMs + 128;
    int tid = threadIdx.x, lane = tid & 31, wid = tid >> 5;
    int b = blockIdx.y, ct = blockIdx.x, c0 = ct * 128;

    if (tid < 128) cMs[tid] = g_colM[b * Qn + tid];
    else if (tid < 256) cms[tid - 128] = cmask[b * Cn + c0 + tid - 128];
    __syncthreads();

    for (int i = tid; i < 2048; i += 512) {
        int r = i >> 4, slot = i & 15;
        const float* pa = &c_g[((size_t)b * Hn + r) * Cn + c0 + slot * 8];
        split8(smem, smem + 32768, r, slot, *(const float4*)pa, *(const float4*)(pa + 4));
        const float* ps = &g_St[((size_t)b * Qn + r) * Cn + c0 + slot * 8];
        float4 s0 = *(const float4*)ps, s1 = *(const float4*)(ps + 4);
        float cM = cMs[r];
        float4 e0, e1;
        e0.x = (cms[slot * 8 + 0] > 0.f) ? __expf(s0.x - cM) : 0.f;
        e0.y = (cms[slot * 8 + 1] > 0.f) ? __expf(s0.y - cM) : 0.f;
        e0.z = (cms[slot * 8 + 2] > 0.f) ? __expf(s0.z - cM) : 0.f;
        e0.w = (cms[slot * 8 + 3] > 0.f) ? __expf(s0.w - cM) : 0.f;
        e1.x = (cms[slot * 8 + 4] > 0.f) ? __expf(s1.x - cM) : 0.f;
        e1.y = (cms[slot * 8 + 5] > 0.f) ? __expf(s1.y - cM) : 0.f;
        e1.z = (cms[slot * 8 + 6] > 0.f) ? __expf(s1.z - cM) : 0.f;
        e1.w = (cms[slot * 8 + 7] > 0.f) ? __expf(s1.w - cM) : 0.f;
        split8(smem + 65536, smem + 98304, r, slot, e0, e1);
    }
    __syncthreads();

    float acc[2][4][4];
#pragma unroll
    for (int i = 0; i < 2; i++)
#pragma unroll
        for (int j = 0; j < 4; j++)
#pragma unroll
            for (int k = 0; k < 4; k++) acc[i][j][k] = 0.f;

    int m0 = (wid >> 2) * 32, n0 = (wid & 3) * 32;
    warp_gemm128(sb, sb + 32768, sb + 65536, sb + 98304, lane, m0, n0, acc);

    int lr = lane >> 2, lc = (lane & 3) * 2;
#pragma unroll
    for (int mf = 0; mf < 2; mf++) {
        int h0 = m0 + mf * 16 + lr, h1 = h0 + 8;
#pragma unroll
        for (int nf = 0; nf < 4; nf++) {
            int col = n0 + nf * 8 + lc;
            *(float2*)&g_qbp[((size_t)(b * NT + ct) * Hn + h0) * Qn + col] =
                make_float2(acc[mf][nf][0], acc[mf][nf][1]);
            *(float2*)&g_qbp[((size_t)(b * NT + ct) * Hn + h1) * Qn + col] =
                make_float2(acc[mf][nf][2], acc[mf][nf][3]);
        }
    }
}

// ---------------- K3b: combine split-K partials ----------------
__global__ void k3b_combine() {
    int idx = blockIdx.x * 256 + threadIdx.x;
    int b = idx >> 14, rem = idx & 16383, q = idx & 127;
    float s = 0.f;
#pragma unroll
    for (int t = 0; t < NT; t++) s += g_qbp[(size_t)(b * NT + t) * 16384 + rem];
    float z = g_colZ[b * Qn + q];
    g_qbT[idx] = (z > 0.f) ? s / z : 0.f;
}

// ---------------- K4: a = E·q^T, bb = E·qb^T; assemble output ----------------
#define K4_SMEM (196608 + 1536)

__global__ __launch_bounds__(512) void k4_out(
    const float* __restrict__ c_g, const float* __restrict__ q_g,
    const float* __restrict__ qmask, float* __restrict__ out)
{
    extern __shared__ __align__(256) char smem[];
    u32 sb = smem_u32(smem);
    float* rms = (float*)(smem + 196608);
    float* qms = rms + 128;
    float* rzs = qms + 128;
    int tid = threadIdx.x, lane = tid & 31, wid = tid >> 5;
    int b = blockIdx.y, ct = blockIdx.x, c0 = ct * 128;

    if (tid < 128) rms[tid] = g_rowM[b * Cn + c0 + tid];
    else if (tid < 256) qms[tid - 128] = qmask[b * Qn + tid - 128];
    else if (tid < 384) {
        float z = g_rowZ[b * Cn + c0 + tid - 256];
        rzs[tid - 256] = (z > 0.f) ? 1.f / z : 0.f;
    }
    __syncthreads();

    // tiles: E hi 0, E lo 32768, Q hi 65536, Q lo 98304, P hi 131072, P lo 163840
    for (int i = tid; i < 2048; i += 512) {
        int r = i >> 4, slot = i & 15;
        const float* ps = &g_S[((size_t)b * Cn + c0 + r) * Qn + slot * 8];
        float4 s0 = *(const float4*)ps, s1 = *(const float4*)(ps + 4);
        float rm = rms[r];
        float4 e0, e1;
        e0.x = (qms[slot * 8 + 0] > 0.f) ? __expf(s0.x - rm) : 0.f;
        e0.y = (qms[slot * 8 + 1] > 0.f) ? __expf(s0.y - rm) : 0.f;
        e0.z = (qms[slot * 8 + 2] > 0.f) ? __expf(s0.z - rm) : 0.f;
        e0.w = (qms[slot * 8 + 3] > 0.f) ? __expf(s0.w - rm) : 0.f;
        e1.x = (qms[slot * 8 + 4] > 0.f) ? __expf(s1.x - rm) : 0.f;
        e1.y = (qms[slot * 8 + 5] > 0.f) ? __expf(s1.y - rm) : 0.f;
        e1.z = (qms[slot * 8 + 6] > 0.f) ? __expf(s1.z - rm) : 0.f;
        e1.w = (qms[slot * 8 + 7] > 0.f) ? __expf(s1.w - rm) : 0.f;
        split8(smem, smem + 32768, r, slot, e0, e1);
        const float* pq = &q_g[((size_t)b * Hn + r) * Qn + slot * 8];
        split8(smem + 65536, smem + 98304, r, slot, *(const float4*)pq, *(const float4*)(pq + 4));
        const float* pp = &g_qbT[((size_t)b * Hn + r) * Qn + slot * 8];
        split8(smem + 131072, smem + 163840, r, slot, *(const float4*)pp, *(const float4*)(pp + 4));
    }
    __syncthreads();

    int m0 = (wid >> 2) * 32, n0 = (wid & 3) * 32;
    int lr = lane >> 2, lc = (lane & 3) * 2;

    // ---- loop 1: a = E @ q^T ----
    {
        float acc[2][4][4];
#pragma unroll
        for (int i = 0; i < 2; i++)
#pragma unroll
            for (int j = 0; j < 4; j++)
#pragma unroll
                for (int k = 0; k < 4; k++) acc[i][j][k] = 0.f;
        warp_gemm128(sb, sb + 32768, sb + 65536, sb + 98304, lane, m0, n0, acc);
        __syncthreads();                       // done reading Q tiles
        float* StA = (float*)(smem + 65536);   // reuse Q region
#pragma unroll
        for (int mf = 0; mf < 2; mf++) {
            int cl0 = m0 + mf * 16 + lr, cl1 = cl0 + 8;
            float rz0 = rzs[cl0], rz1 = rzs[cl1];
#pragma unroll
            for (int nf = 0; nf < 4; nf++) {
                int h = n0 + nf * 8 + lc;
                StA[(h << 7) + ((cl0 ^ h) & 127)]             = acc[mf][nf][0] * rz0;
                StA[((h + 1) << 7) + ((cl0 ^ (h + 1)) & 127)] = acc[mf][nf][1] * rz0;
                StA[(h << 7) + ((cl1 ^ h) & 127)]             = acc[mf][nf][2] * rz1;
                StA[((h + 1) << 7) + ((cl1 ^ (h + 1)) & 127)] = acc[mf][nf][3] * rz1;
            }
        }
    }

    // ---- loop 2: bb = E @ qb^T ----
    {
        float acc[2][4][4];
#pragma unroll
        for (int i = 0; i < 2; i++)
#pragma unroll
            for (int j = 0; j < 4; j++)
#pragma unroll
                for (int k = 0; k < 4; k++) acc[i][j][k] = 0.f;
        warp_gemm128(sb, sb + 32768, sb + 131072, sb + 163840, lane, m0, n0, acc);
        __syncthreads();                     // done reading E tiles
        float* StB = (float*)smem;           // reuse E region
#pragma unroll
        for (int mf = 0; mf < 2; mf++) {
            int cl0 = m0 + mf * 16 + lr, cl1 = cl0 + 8;
            float rz0 = rzs[cl0], rz1 = rzs[cl1];
#pragma unroll
            for (int nf = 0; nf < 4; nf++) {
                int h = n0 + nf * 8 + lc;
                StB[(h << 7) + ((cl0 ^ h) & 127)]             = acc[mf][nf][0] * rz0;
                StB[((h + 1) << 7) + ((cl0 ^ (h + 1)) & 127)] = acc[mf][nf][1] * rz0;
                StB[(h << 7) + ((cl1 ^ h) & 127)]             = acc[mf][nf][2] * rz1;
                StB[((h + 1) << 7) + ((cl1 ^ (h + 1)) & 127)] = acc[mf][nf][3] * rz1;
            }
        }
    }
    __syncthreads();

    float* StA = (float*)(smem + 65536);
    float* StB = (float*)smem;
    const size_t HC = (size_t)Hn * Cn;
    for (int i = tid; i < 16384; i += 512) {
        int h = i >> 7, cc = i & 127;
        float a  = StA[(h << 7) + ((cc ^ h) & 127)];
        float bb = StB[(h << 7) + ((cc ^ h) & 127)];
        float cv = c_g[((size_t)b * Hn + h) * Cn + c0 + cc];
        size_t o = (size_t)b * 4 * HC + (size_t)h * Cn + c0 + cc;
        out[o]          = cv;
        out[o + HC]     = a;
        out[o + 2 * HC] = cv * a;
        out[o + 3 * HC] = cv * bb;
    }
}

// ---------------- launch ----------------
extern "C" void kernel_launch(void* const* d_in, const int* in_sizes, int n_in,
                              void* d_out, int out_size)
{
    const float* c     = (const float*)d_in[0];
    const float* q     = (const float*)d_in[1];
    const float* cmask = (const float*)d_in[2];
    const float* qmask = (const float*)d_in[3];
    const float* wc    = (const float*)d_in[4];
    const float* wq    = (const float*)d_in[5];
    const float* wcq   = (const float*)d_in[6];
    const float* bias  = (const float*)d_in[7];
    float* out = (float*)d_out;

    cudaFuncSetAttribute(k1_score, cudaFuncAttributeMaxDynamicSharedMemorySize, K1_SMEM);
    cudaFuncSetAttribute(k3_qbp,   cudaFuncAttributeMaxDynamicSharedMemorySize, K3_SMEM);
    cudaFuncSetAttribute(k4_out,   cudaFuncAttributeMaxDynamicSharedMemorySize, K4_SMEM);

    ktrans_c<<<dim3(Cn / 32, Hn / 32, Bn), dim3(32, 8)>>>(c);
    ktrans_q<<<dim3(Qn / 32, Hn / 32, Bn), dim3(32, 8)>>>(q);
    k1_score<<<dim3(NT, Bn), 512, K1_SMEM>>>(wc, wq, wcq, bias);
    kstat_row<<<dim3(Cn / 8, Bn), 256>>>(qmask);
    kstat_col<<<dim3(Qn / 8, Bn), 256>>>(cmask);
    k3_qbp<<<dim3(NT, Bn), 512, K3_SMEM>>>(c, cmask);
    k3b_combine<<<(Bn * Qn * Hn) / 256, 256>>>();
    k4_out<<<dim3(NT, Bn), 512, K4_SMEM>>>(c, q, qmask, out);
}

// round 6
// speedup vs baseline: 2.3116x; 1.0071x over previous
#include <cuda_runtime.h>
#include <cuda_bf16.h>

#define Bn 64
#define Hn 128
#define Cn 1024
#define Qn 128
#define NT 8

typedef unsigned int u32;

// ---------------- scratch ----------------
__device__ float g_S  [Bn * Cn * Qn];
__device__ float g_St [Bn * Qn * Cn];
__device__ float g_cT [Bn * Cn * Hn];
__device__ float g_qT [Bn * Qn * Hn];
__device__ float g_rowM[Bn * Cn];
__device__ float g_rowZ[Bn * Cn];
__device__ float g_pM [Bn * NT * Qn];
__device__ float g_pZ [Bn * NT * Qn];
__device__ float g_colM[Bn * Qn];
__device__ float g_colZ[Bn * Qn];
__device__ float g_qbp2[Bn * 2 * Hn * Qn];
__device__ float g_qbT [Bn * Hn * Qn];

// ---------------- helpers ----------------
__device__ __forceinline__ u32 smem_u32(const void* p) {
    u32 a;
    asm("{ .reg .u64 t; cvta.to.shared.u64 t, %1; cvt.u32.u64 %0, t; }" : "=r"(a) : "l"(p));
    return a;
}
__device__ __forceinline__ void ldsm4(u32 a, u32* r) {
    asm volatile("ldmatrix.sync.aligned.m8n8.x4.shared.b16 {%0,%1,%2,%3}, [%4];"
        : "=r"(r[0]), "=r"(r[1]), "=r"(r[2]), "=r"(r[3]) : "r"(a));
}
__device__ __forceinline__ void mmabf(float* d, const u32* a, u32 b0, u32 b1) {
    asm volatile("mma.sync.aligned.m16n8k16.row.col.f32.bf16.bf16.f32 "
        "{%0,%1,%2,%3},{%4,%5,%6,%7},{%8,%9},{%0,%1,%2,%3};"
        : "+f"(d[0]), "+f"(d[1]), "+f"(d[2]), "+f"(d[3])
        : "r"(a[0]), "r"(a[1]), "r"(a[2]), "r"(a[3]), "r"(b0), "r"(b1));
}

// split 8 fp32 into bf16 hi + bf16 lo, store 16B at swizzled slot of K-minor tile
__device__ __forceinline__ void split8(char* hi, char* lo, int r, int slot,
                                       float4 v0, float4 v1)
{
    float f[8] = {v0.x, v0.y, v0.z, v0.w, v1.x, v1.y, v1.z, v1.w};
    u32 H[4], L[4];
#pragma unroll
    for (int j = 0; j < 4; j++) {
        float a = f[2 * j], b = f[2 * j + 1];
        __nv_bfloat16 ha = __float2bfloat16(a), hb = __float2bfloat16(b);
        float fa = __bfloat162float(ha), fb = __bfloat162float(hb);
        __nv_bfloat162 hp; hp.x = ha; hp.y = hb;
        H[j] = *(u32*)&hp;
        __nv_bfloat162 lp = __floats2bfloat162_rn(a - fa, b - fb);
        L[j] = *(u32*)&lp;
    }
    u32 off = (u32)r * 256 + (u32)((slot ^ (r & 7)) << 4);
    *(uint4*)(hi + off) = make_uint4(H[0], H[1], H[2], H[3]);
    *(uint4*)(lo + off) = make_uint4(L[0], L[1], L[2], L[3]);
}

// 128x128x128 warp-tile GEMM (accumulating): D[m][n] += A[m][k]*B[n][k]
__device__ __forceinline__ void warp_gemm128(u32 ah, u32 al, u32 bh, u32 bl,
                                             int lane, int m0, int n0,
                                             float acc[2][4][4])
{
    int rA = lane & 15, hi16 = lane >> 4;
    int rBl = (lane & 7) + ((lane >> 4) << 3);
    int kh = (lane >> 3) & 1;
    int rowA[2] = {m0 + rA, m0 + 16 + rA};
    int rowB[2] = {n0 + rBl, n0 + 16 + rBl};
#pragma unroll
    for (int ks = 0; ks < 8; ks++) {
        u32 AH[2][4], AL[2][4], BH[2][4], BL[2][4];
#pragma unroll
        for (int f = 0; f < 2; f++) {
            u32 sa = (u32)rowA[f] * 256 + (u32)((((ks << 1) + hi16) ^ (rowA[f] & 7)) << 4);
            ldsm4(ah + sa, AH[f]);
            ldsm4(al + sa, AL[f]);
            u32 sb = (u32)rowB[f] * 256 + (u32)((((ks << 1) + kh) ^ (rowB[f] & 7)) << 4);
            ldsm4(bh + sb, BH[f]);
            ldsm4(bl + sb, BL[f]);
        }
#pragma unroll
        for (int mf = 0; mf < 2; mf++)
#pragma unroll
            for (int nh = 0; nh < 2; nh++)
#pragma unroll
                for (int no = 0; no < 2; no++) {
                    float* d = acc[mf][nh * 2 + no];
                    mmabf(d, AH[mf], BH[nh][2 * no], BH[nh][2 * no + 1]);
                    mmabf(d, AH[mf], BL[nh][2 * no], BL[nh][2 * no + 1]);
                    mmabf(d, AL[mf], BH[nh][2 * no], BH[nh][2 * no + 1]);
                }
    }
}

// ---------------- K0: transposes (B,H,L) -> (B,L,H) ----------------
__global__ void ktrans_c(const float* __restrict__ in) {
    __shared__ float t[32][33];
    int b = blockIdx.z, l0 = blockIdx.x * 32, h0 = blockIdx.y * 32;
    int tx = threadIdx.x, ty = threadIdx.y;
#pragma unroll
    for (int i = 0; i < 32; i += 8)
        t[ty + i][tx] = in[((size_t)b * Hn + h0 + ty + i) * Cn + l0 + tx];
    __syncthreads();
#pragma unroll
    for (int i = 0; i < 32; i += 8)
        g_cT[((size_t)b * Cn + l0 + ty + i) * Hn + h0 + tx] = t[tx][ty + i];
}
__global__ void ktrans_q(const float* __restrict__ in) {
    __shared__ float t[32][33];
    int b = blockIdx.z, l0 = blockIdx.x * 32, h0 = blockIdx.y * 32;
    int tx = threadIdx.x, ty = threadIdx.y;
#pragma unroll
    for (int i = 0; i < 32; i += 8)
        t[ty + i][tx] = in[((size_t)b * Hn + h0 + ty + i) * Qn + l0 + tx];
    __syncthreads();
#pragma unroll
    for (int i = 0; i < 32; i += 8)
        g_qT[((size_t)b * Qn + l0 + ty + i) * Hn + h0 + tx] = t[tx][ty + i];
}

// ---------------- K1: S GEMM + S/S^T writes + fused softmax stats ----------
#define K1_SMEM (131072 + 2048 + 4096)

__global__ __launch_bounds__(512) void k1_score(
    const float* __restrict__ cmask, const float* __restrict__ qmask,
    const float* __restrict__ wc, const float* __restrict__ wq,
    const float* __restrict__ wcq, const float* __restrict__ bias)
{
    extern __shared__ __align__(256) char smem[];
    u32 sb = smem_u32(smem);
    float* s0s  = (float*)(smem + 131072);
    float* s1s  = s0s + 128;
    float* qms  = s1s + 128;
    float* cms  = qms + 128;
    float* red1 = (float*)(smem + 131072 + 2048);   // [4][128]
    float* red2 = red1 + 512;                       // [4][128]
    int tid = threadIdx.x, lane = tid & 31, wid = tid >> 5;
    int b = blockIdx.y, ct = blockIdx.x, c0 = ct * 128;

    for (int i = tid; i < 2048; i += 512) {
        int r = i >> 4, slot = i & 15;
        const float* pa = &g_cT[((size_t)b * Cn + c0 + r) * Hn + slot * 8];
        split8(smem, smem + 32768, r, slot, *(const float4*)pa, *(const float4*)(pa + 4));
        const float* pb = &g_qT[((size_t)b * Qn + r) * Hn + slot * 8];
        float4 v0 = *(const float4*)pb, v1 = *(const float4*)(pb + 4);
        float4 w0 = *(const float4*)&wcq[slot * 8], w1 = *(const float4*)&wcq[slot * 8 + 4];
        v0.x *= w0.x; v0.y *= w0.y; v0.z *= w0.z; v0.w *= w0.w;
        v1.x *= w1.x; v1.y *= w1.y; v1.z *= w1.z; v1.w *= w1.w;
        split8(smem + 65536, smem + 98304, r, slot, v0, v1);
    }
    if (tid < 128) {
        const float* row = &g_cT[((size_t)b * Cn + c0 + tid) * Hn];
        float a = 0.f;
#pragma unroll 8
        for (int h = 0; h < 128; h++) a += row[h] * wc[h];
        s0s[tid] = a + bias[0];
    } else if (tid < 256) {
        int qq = tid - 128;
        const float* row = &g_qT[((size_t)b * Qn + qq) * Hn];
        float a = 0.f;
#pragma unroll 8
        for (int h = 0; h < 128; h++) a += row[h] * wq[h];
        s1s[qq] = a;
    } else if (tid < 384) {
        qms[tid - 256] = qmask[b * Qn + tid - 256];
    } else {
        cms[tid - 384] = cmask[b * Cn + c0 + tid - 384];
    }
    __syncthreads();

    float acc[2][4][4];
#pragma unroll
    for (int i = 0; i < 2; i++)
#pragma unroll
        for (int j = 0; j < 4; j++)
#pragma unroll
            for (int k = 0; k < 4; k++) acc[i][j][k] = 0.f;

    int m0 = (wid >> 2) * 32, n0 = (wid & 3) * 32;
    warp_gemm128(sb, sb + 32768, sb + 65536, sb + 98304, lane, m0, n0, acc);

    int lr = lane >> 2, lc2 = (lane & 3) * 2;

    // finalize S values in-place: acc += s0[row] + s1[col]
#pragma unroll
    for (int mf = 0; mf < 2; mf++) {
        int r0 = m0 + mf * 16 + lr, r1 = r0 + 8;
        float s0a = s0s[r0], s0b = s0s[r1];
#pragma unroll
        for (int nf = 0; nf < 4; nf++) {
            int col = n0 + nf * 8 + lc2;
            float s1a = s1s[col], s1b = s1s[col + 1];
            acc[mf][nf][0] += s0a + s1a;
            acc[mf][nf][1] += s0a + s1b;
            acc[mf][nf][2] += s0b + s1a;
            acc[mf][nf][3] += s0b + s1b;
        }
    }

    // write S [c][q]
#pragma unroll
    for (int mf = 0; mf < 2; mf++) {
        int r0 = m0 + mf * 16 + lr, r1 = r0 + 8;
#pragma unroll
        for (int nf = 0; nf < 4; nf++) {
            int col = n0 + nf * 8 + lc2;
            *(float2*)&g_S[((size_t)b * Cn + c0 + r0) * Qn + col] =
                make_float2(acc[mf][nf][0], acc[mf][nf][1]);
            *(float2*)&g_S[((size_t)b * Cn + c0 + r1) * Qn + col] =
                make_float2(acc[mf][nf][2], acc[mf][nf][3]);
        }
    }

    // masks
    bool qm0[4], qm1[4];
#pragma unroll
    for (int nf = 0; nf < 4; nf++) {
        qm0[nf] = qms[n0 + nf * 8 + lc2] > 0.f;
        qm1[nf] = qms[n0 + nf * 8 + lc2 + 1] > 0.f;
    }
    bool cmv[2][2];
#pragma unroll
    for (int mf = 0; mf < 2; mf++) {
        cmv[mf][0] = cms[m0 + mf * 16 + lr] > 0.f;
        cmv[mf][1] = cms[m0 + mf * 16 + 8 + lr] > 0.f;
    }

    // ---- row stats (softmax over q) ----
    float rmx[2][2];
#pragma unroll
    for (int mf = 0; mf < 2; mf++) { rmx[mf][0] = -1e30f; rmx[mf][1] = -1e30f; }
#pragma unroll
    for (int mf = 0; mf < 2; mf++)
#pragma unroll
        for (int nf = 0; nf < 4; nf++) {
            if (qm0[nf]) {
                rmx[mf][0] = fmaxf(rmx[mf][0], acc[mf][nf][0]);
                rmx[mf][1] = fmaxf(rmx[mf][1], acc[mf][nf][2]);
            }
            if (qm1[nf]) {
                rmx[mf][0] = fmaxf(rmx[mf][0], acc[mf][nf][1]);
                rmx[mf][1] = fmaxf(rmx[mf][1], acc[mf][nf][3]);
            }
        }
#pragma unroll
    for (int mf = 0; mf < 2; mf++)
#pragma unroll
        for (int h = 0; h < 2; h++) {
            rmx[mf][h] = fmaxf(rmx[mf][h], __shfl_xor_sync(~0u, rmx[mf][h], 1));
            rmx[mf][h] = fmaxf(rmx[mf][h], __shfl_xor_sync(~0u, rmx[mf][h], 2));
        }
    if ((lane & 3) == 0)
#pragma unroll
        for (int mf = 0; mf < 2; mf++)
#pragma unroll
            for (int h = 0; h < 2; h++)
                red1[(wid & 3) * 128 + m0 + mf * 16 + h * 8 + lr] = rmx[mf][h];
    __syncthreads();

    float rowMv[2][2];
#pragma unroll
    for (int mf = 0; mf < 2; mf++)
#pragma unroll
        for (int h = 0; h < 2; h++) {
            int r = m0 + mf * 16 + h * 8 + lr;
            float m = red1[r];
#pragma unroll
            for (int g = 1; g < 4; g++) m = fmaxf(m, red1[g * 128 + r]);
            rowMv[mf][h] = m;
        }
    float rzz[2][2] = {{0.f, 0.f}, {0.f, 0.f}};
#pragma unroll
    for (int mf = 0; mf < 2; mf++)
#pragma unroll
        for (int nf = 0; nf < 4; nf++) {
            if (qm0[nf]) {
                rzz[mf][0] += __expf(acc[mf][nf][0] - rowMv[mf][0]);
                rzz[mf][1] += __expf(acc[mf][nf][2] - rowMv[mf][1]);
            }
            if (qm1[nf]) {
                rzz[mf][0] += __expf(acc[mf][nf][1] - rowMv[mf][0]);
                rzz[mf][1] += __expf(acc[mf][nf][3] - rowMv[mf][1]);
            }
        }
#pragma unroll
    for (int mf = 0; mf < 2; mf++)
#pragma unroll
        for (int h = 0; h < 2; h++) {
            rzz[mf][h] += __shfl_xor_sync(~0u, rzz[mf][h], 1);
            rzz[mf][h] += __shfl_xor_sync(~0u, rzz[mf][h], 2);
        }
    if ((lane & 3) == 0)
#pragma unroll
        for (int mf = 0; mf < 2; mf++)
#pragma unroll
            for (int h = 0; h < 2; h++)
                red2[(wid & 3) * 128 + m0 + mf * 16 + h * 8 + lr] = rzz[mf][h];
    __syncthreads();

    if ((wid & 3) == 0 && (lane & 3) == 0) {
#pragma unroll
        for (int mf = 0; mf < 2; mf++)
#pragma unroll
            for (int h = 0; h < 2; h++) {
                int r = m0 + mf * 16 + h * 8 + lr;
                float z = red2[r] + red2[128 + r] + red2[256 + r] + red2[384 + r];
                g_rowM[b * Cn + c0 + r] = rowMv[mf][h];
                g_rowZ[b * Cn + c0 + r] = z;
            }
    }
    __syncthreads();

    // ---- column partial stats (softmax over c, this tile) ----
    float cmx[4][2];
#pragma unroll
    for (int nf = 0; nf < 4; nf++) { cmx[nf][0] = -1e30f; cmx[nf][1] = -1e30f; }
#pragma unroll
    for (int mf = 0; mf < 2; mf++)
#pragma unroll
        for (int nf = 0; nf < 4; nf++) {
            if (cmv[mf][0]) {
                cmx[nf][0] = fmaxf(cmx[nf][0], acc[mf][nf][0]);
                cmx[nf][1] = fmaxf(cmx[nf][1], acc[mf][nf][1]);
            }
            if (cmv[mf][1]) {
                cmx[nf][0] = fmaxf(cmx[nf][0], acc[mf][nf][2]);
                cmx[nf][1] = fmaxf(cmx[nf][1], acc[mf][nf][3]);
            }
        }
#pragma unroll
    for (int nf = 0; nf < 4; nf++)
#pragma unroll
        for (int v = 0; v < 2; v++) {
            cmx[nf][v] = fmaxf(cmx[nf][v], __shfl_xor_sync(~0u, cmx[nf][v], 4));
            cmx[nf][v] = fmaxf(cmx[nf][v], __shfl_xor_sync(~0u, cmx[nf][v], 8));
            cmx[nf][v] = fmaxf(cmx[nf][v], __shfl_xor_sync(~0u, cmx[nf][v], 16));
        }
    if (lr == 0)
#pragma unroll
        for (int nf = 0; nf < 4; nf++) {
            red1[(wid >> 2) * 128 + n0 + nf * 8 + lc2]     = cmx[nf][0];
            red1[(wid >> 2) * 128 + n0 + nf * 8 + lc2 + 1] = cmx[nf][1];
        }
    __syncthreads();

    float pMv[4][2];
#pragma unroll
    for (int nf = 0; nf < 4; nf++)
#pragma unroll
        for (int v = 0; v < 2; v++) {
            int col = n0 + nf * 8 + lc2 + v;
            float m = red1[col];
#pragma unroll
            for (int g = 1; g < 4; g++) m = fmaxf(m, red1[g * 128 + col]);
            pMv[nf][v] = m;
        }
    float czz[4][2] = {{0,0},{0,0},{0,0},{0,0}};
#pragma unroll
    for (int mf = 0; mf < 2; mf++)
#pragma unroll
        for (int nf = 0; nf < 4; nf++) {
            if (cmv[mf][0]) {
                czz[nf][0] += __expf(acc[mf][nf][0] - pMv[nf][0]);
                czz[nf][1] += __expf(acc[mf][nf][1] - pMv[nf][1]);
            }
            if (cmv[mf][1]) {
                czz[nf][0] += __expf(acc[mf][nf][2] - pMv[nf][0]);
                czz[nf][1] += __expf(acc[mf][nf][3] - pMv[nf][1]);
            }
        }
#pragma unroll
    for (int nf = 0; nf < 4; nf++)
#pragma unroll
        for (int v = 0; v < 2; v++) {
            czz[nf][v] += __shfl_xor_sync(~0u, czz[nf][v], 4);
            czz[nf][v] += __shfl_xor_sync(~0u, czz[nf][v], 8);
            czz[nf][v] += __shfl_xor_sync(~0u, czz[nf][v], 16);
        }
    if (lr == 0)
#pragma unroll
        for (int nf = 0; nf < 4; nf++) {
            red2[(wid >> 2) * 128 + n0 + nf * 8 + lc2]     = czz[nf][0];
            red2[(wid >> 2) * 128 + n0 + nf * 8 + lc2 + 1] = czz[nf][1];
        }
    __syncthreads();

    if ((wid >> 2) == 0 && lr == 0) {
#pragma unroll
        for (int nf = 0; nf < 4; nf++)
#pragma unroll
            for (int v = 0; v < 2; v++) {
                int col = n0 + nf * 8 + lc2 + v;
                float z = red2[col] + red2[128 + col] + red2[256 + col] + red2[384 + col];
                g_pM[(b * NT + ct) * Qn + col] = pMv[nf][v];
                g_pZ[(b * NT + ct) * Qn + col] = z;
            }
    }

    // ---- stage S^T and write coalesced ----
    float* Sts = (float*)smem;   // tiles dead (all warps past gemm via stats syncs)
#pragma unroll
    for (int mf = 0; mf < 2; mf++) {
        int r0 = m0 + mf * 16 + lr, r1 = r0 + 8;
#pragma unroll
        for (int nf = 0; nf < 4; nf++) {
            int col = n0 + nf * 8 + lc2;
            Sts[col * 128 + ((r0 ^ col) & 127)]             = acc[mf][nf][0];
            Sts[(col + 1) * 128 + ((r0 ^ (col + 1)) & 127)] = acc[mf][nf][1];
            Sts[col * 128 + ((r1 ^ col) & 127)]             = acc[mf][nf][2];
            Sts[(col + 1) * 128 + ((r1 ^ (col + 1)) & 127)] = acc[mf][nf][3];
        }
    }
    __syncthreads();
    for (int i = tid; i < 16384; i += 512) {
        int q = i >> 7, cc = i & 127;
        g_St[((size_t)b * Qn + q) * Cn + c0 + cc] = Sts[(q << 7) + ((cc ^ q) & 127)];
    }
}

// ---------------- kcomb: combine column partial stats ----------------
__global__ void kcomb() {
    int b = blockIdx.x, q = threadIdx.x;
    float m = -3.4e38f;
#pragma unroll
    for (int t = 0; t < NT; t++) m = fmaxf(m, g_pM[(b * NT + t) * Qn + q]);
    float z = 0.f;
#pragma unroll
    for (int t = 0; t < NT; t++)
        z += g_pZ[(b * NT + t) * Qn + q] * __expf(g_pM[(b * NT + t) * Qn + q] - m);
    g_colM[b * Qn + q] = m;
    g_colZ[b * Qn + q] = z;
}

// ---------------- K3: qb^T partials = c · E2^T, split-K over 2 halves --------
#define K3_SMEM 131072

__global__ __launch_bounds__(512) void k3_qb(
    const float* __restrict__ c_g, const float* __restrict__ cmask)
{
    extern __shared__ __align__(256) char smem[];
    u32 sb = smem_u32(smem);
    int tid = threadIdx.x, lane = tid & 31, wid = tid >> 5;
    int b = blockIdx.y, half = blockIdx.x;

    float acc[2][4][4];
#pragma unroll
    for (int i = 0; i < 2; i++)
#pragma unroll
        for (int j = 0; j < 4; j++)
#pragma unroll
            for (int k = 0; k < 4; k++) acc[i][j][k] = 0.f;

    int m0 = (wid >> 2) * 32, n0 = (wid & 3) * 32;

    for (int t = 0; t < 4; t++) {
        int c0 = (half * 4 + t) * 128;
        __syncthreads();
        for (int i = tid; i < 2048; i += 512) {
            int r = i >> 4, slot = i & 15;
            const float* pa = &c_g[((size_t)b * Hn + r) * Cn + c0 + slot * 8];
            split8(smem, smem + 32768, r, slot, *(const float4*)pa, *(const float4*)(pa + 4));
            const float* ps = &g_St[((size_t)b * Qn + r) * Cn + c0 + slot * 8];
            float4 s0 = *(const float4*)ps, s1 = *(const float4*)(ps + 4);
            float4 cm0 = *(const float4*)&cmask[b * Cn + c0 + slot * 8];
            float4 cm1 = *(const float4*)&cmask[b * Cn + c0 + slot * 8 + 4];
            float cM = g_colM[b * Qn + r];
            float4 e0, e1;
            e0.x = (cm0.x > 0.f) ? __expf(s0.x - cM) : 0.f;
            e0.y = (cm0.y > 0.f) ? __expf(s0.y - cM) : 0.f;
            e0.z = (cm0.z > 0.f) ? __expf(s0.z - cM) : 0.f;
            e0.w = (cm0.w > 0.f) ? __expf(s0.w - cM) : 0.f;
            e1.x = (cm1.x > 0.f) ? __expf(s1.x - cM) : 0.f;
            e1.y = (cm1.y > 0.f) ? __expf(s1.y - cM) : 0.f;
            e1.z = (cm1.z > 0.f) ? __expf(s1.z - cM) : 0.f;
            e1.w = (cm1.w > 0.f) ? __expf(s1.w - cM) : 0.f;
            split8(smem + 65536, smem + 98304, r, slot, e0, e1);
        }
        __syncthreads();
        warp_gemm128(sb, sb + 32768, sb + 65536, sb + 98304, lane, m0, n0, acc);
    }

    int lr = lane >> 2, lc2 = (lane & 3) * 2;
#pragma unroll
    for (int mf = 0; mf < 2; mf++) {
        int h0 = m0 + mf * 16 + lr, h1 = h0 + 8;
#pragma unroll
        for (int nf = 0; nf < 4; nf++) {
            int col = n0 + nf * 8 + lc2;
            *(float2*)&g_qbp2[((size_t)(b * 2 + half) * Hn + h0) * Qn + col] =
                make_float2(acc[mf][nf][0], acc[mf][nf][1]);
            *(float2*)&g_qbp2[((size_t)(b * 2 + half) * Hn + h1) * Qn + col] =
                make_float2(acc[mf][nf][2], acc[mf][nf][3]);
        }
    }
}

// ---------------- K3b: combine 2 partials, normalize by colZ ----------------
__global__ void k3b_combine() {
    int idx = blockIdx.x * 256 + threadIdx.x;
    int b = idx >> 14, rem = idx & 16383, q = idx & 127;
    float s = g_qbp2[(size_t)(b * 2) * 16384 + rem] + g_qbp2[(size_t)(b * 2 + 1) * 16384 + rem];
    float z = g_colZ[b * Qn + q];
    g_qbT[idx] = (z > 0.f) ? s / z : 0.f;
}

// ---------------- K4: a = E·q^T, bb = E·qb^T; assemble output ----------------
#define K4_SMEM (196608 + 1536)

__global__ __launch_bounds__(512) void k4_out(
    const float* __restrict__ c_g, const float* __restrict__ q_g,
    const float* __restrict__ qmask, float* __restrict__ out)
{
    extern __shared__ __align__(256) char smem[];
    u32 sb = smem_u32(smem);
    float* rms = (float*)(smem + 196608);
    float* qms = rms + 128;
    float* rzs = qms + 128;
    int tid = threadIdx.x, lane = tid & 31, wid = tid >> 5;
    int b = blockIdx.y, ct = blockIdx.x, c0 = ct * 128;

    if (tid < 128) rms[tid] = g_rowM[b * Cn + c0 + tid];
    else if (tid < 256) qms[tid - 128] = qmask[b * Qn + tid - 128];
    else if (tid < 384) {
        float z = g_rowZ[b * Cn + c0 + tid - 256];
        rzs[tid - 256] = (z > 0.f) ? 1.f / z : 0.f;
    }
    __syncthreads();

    for (int i = tid; i < 2048; i += 512) {
        int r = i >> 4, slot = i & 15;
        const float* ps = &g_S[((size_t)b * Cn + c0 + r) * Qn + slot * 8];
        float4 s0 = *(const float4*)ps, s1 = *(const float4*)(ps + 4);
        float rm = rms[r];
        float4 e0, e1;
        e0.x = (qms[slot * 8 + 0] > 0.f) ? __expf(s0.x - rm) : 0.f;
        e0.y = (qms[slot * 8 + 1] > 0.f) ? __expf(s0.y - rm) : 0.f;
        e0.z = (qms[slot * 8 + 2] > 0.f) ? __expf(s0.z - rm) : 0.f;
        e0.w = (qms[slot * 8 + 3] > 0.f) ? __expf(s0.w - rm) : 0.f;
        e1.x = (qms[slot * 8 + 4] > 0.f) ? __expf(s1.x - rm) : 0.f;
        e1.y = (qms[slot * 8 + 5] > 0.f) ? __expf(s1.y - rm) : 0.f;
        e1.z = (qms[slot * 8 + 6] > 0.f) ? __expf(s1.z - rm) : 0.f;
        e1.w = (qms[slot * 8 + 7] > 0.f) ? __expf(s1.w - rm) : 0.f;
        split8(smem, smem + 32768, r, slot, e0, e1);
        const float* pq = &q_g[((size_t)b * Hn + r) * Qn + slot * 8];
        split8(smem + 65536, smem + 98304, r, slot, *(const float4*)pq, *(const float4*)(pq + 4));
        const float* pp = &g_qbT[((size_t)b * Hn + r) * Qn + slot * 8];
        split8(smem + 131072, smem + 163840, r, slot, *(const float4*)pp, *(const float4*)(pp + 4));
    }
    __syncthreads();

    int m0 = (wid >> 2) * 32, n0 = (wid & 3) * 32;
    int lr = lane >> 2, lc = (lane & 3) * 2;

    {
        float acc[2][4][4];
#pragma unroll
        for (int i = 0; i < 2; i++)
#pragma unroll
            for (int j = 0; j < 4; j++)
#pragma unroll
                for (int k = 0; k < 4; k++) acc[i][j][k] = 0.f;
        warp_gemm128(sb, sb + 32768, sb + 65536, sb + 98304, lane, m0, n0, acc);
        __syncthreads();
        float* StA = (float*)(smem + 65536);
#pragma unroll
        for (int mf = 0; mf < 2; mf++) {
            int cl0 = m0 + mf * 16 + lr, cl1 = cl0 + 8;
            float rz0 = rzs[cl0], rz1 = rzs[cl1];
#pragma unroll
            for (int nf = 0; nf < 4; nf++) {
                int h = n0 + nf * 8 + lc;
                StA[(h << 7) + ((cl0 ^ h) & 127)]             = acc[mf][nf][0] * rz0;
                StA[((h + 1) << 7) + ((cl0 ^ (h + 1)) & 127)] = acc[mf][nf][1] * rz0;
                StA[(h << 7) + ((cl1 ^ h) & 127)]             = acc[mf][nf][2] * rz1;
                StA[((h + 1) << 7) + ((cl1 ^ (h + 1)) & 127)] = acc[mf][nf][3] * rz1;
            }
        }
    }
    {
        float acc[2][4][4];
#pragma unroll
        for (int i = 0; i < 2; i++)
#pragma unroll
            for (int j = 0; j < 4; j++)
#pragma unroll
                for (int k = 0; k < 4; k++) acc[i][j][k] = 0.f;
        warp_gemm128(sb, sb + 32768, sb + 131072, sb + 163840, lane, m0, n0, acc);
        __syncthreads();
        float* StB = (float*)smem;
#pragma unroll
        for (int mf = 0; mf < 2; mf++) {
            int cl0 = m0 + mf * 16 + lr, cl1 = cl0 + 8;
            float rz0 = rzs[cl0], rz1 = rzs[cl1];
#pragma unroll
            for (int nf = 0; nf < 4; nf++) {
                int h = n0 + nf * 8 + lc;
                StB[(h << 7) + ((cl0 ^ h) & 127)]             = acc[mf][nf][0] * rz0;
                StB[((h + 1) << 7) + ((cl0 ^ (h + 1)) & 127)] = acc[mf][nf][1] * rz0;
                StB[(h << 7) + ((cl1 ^ h) & 127)]             = acc[mf][nf][2] * rz1;
                StB[((h + 1) << 7) + ((cl1 ^ (h + 1)) & 127)] = acc[mf][nf][3] * rz1;
            }
        }
    }
    __syncthreads();

    float* StA = (float*)(smem + 65536);
    float* StB = (float*)smem;
    const size_t HC = (size_t)Hn * Cn;
    for (int i = tid; i < 16384; i += 512) {
        int h = i >> 7, cc = i & 127;
        float a  = StA[(h << 7) + ((cc ^ h) & 127)];
        float bb = StB[(h << 7) + ((cc ^ h) & 127)];
        float cv = c_g[((size_t)b * Hn + h) * Cn + c0 + cc];
        size_t o = (size_t)b * 4 * HC + (size_t)h * Cn + c0 + cc;
        out[o]          = cv;
        out[o + HC]     = a;
        out[o + 2 * HC] = cv * a;
        out[o + 3 * HC] = cv * bb;
    }
}

// ---------------- launch ----------------
extern "C" void kernel_launch(void* const* d_in, const int* in_sizes, int n_in,
                              void* d_out, int out_size)
{
    const float* c     = (const float*)d_in[0];
    const float* q     = (const float*)d_in[1];
    const float* cmask = (const float*)d_in[2];
    const float* qmask = (const float*)d_in[3];
    const float* wc    = (const float*)d_in[4];
    const float* wq    = (const float*)d_in[5];
    const float* wcq   = (const float*)d_in[6];
    const float* bias  = (const float*)d_in[7];
    float* out = (float*)d_out;

    cudaFuncSetAttribute(k1_score, cudaFuncAttributeMaxDynamicSharedMemorySize, K1_SMEM);
    cudaFuncSetAttribute(k3_qb,    cudaFuncAttributeMaxDynamicSharedMemorySize, K3_SMEM);
    cudaFuncSetAttribute(k4_out,   cudaFuncAttributeMaxDynamicSharedMemorySize, K4_SMEM);

    ktrans_c<<<dim3(Cn / 32, Hn / 32, Bn), dim3(32, 8)>>>(c);
    ktrans_q<<<dim3(Qn / 32, Hn / 32, Bn), dim3(32, 8)>>>(q);
    k1_score<<<dim3(NT, Bn), 512, K1_SMEM>>>(cmask, qmask, wc, wq, wcq, bias);
    kcomb<<<Bn, Qn>>>();
    k3_qb<<<dim3(2, Bn), 512, K3_SMEM>>>(c, cmask);
    k3b_combine<<<(Bn * Qn * Hn) / 256, 256>>>();
    k4_out<<<dim3(NT, Bn), 512, K4_SMEM>>>(c, q, qmask, out);
}

// round 7
// speedup vs baseline: 3.0015x; 1.2984x over previous
#include <cuda_runtime.h>
#include <cuda_bf16.h>

#define Bn 64
#define Hn 128
#define Cn 1024
#define Qn 128
#define NT 8

typedef unsigned int u32;

// ---------------- scratch ----------------
__device__ float g_S  [Bn * Cn * Qn];
__device__ float g_rowM[Bn * Cn];
__device__ float g_rowZ[Bn * Cn];
__device__ float g_pM [Bn * NT * Qn];
__device__ float g_pZ [Bn * NT * Qn];
__device__ float g_qbp2[Bn * 2 * Hn * Qn];

// ---------------- helpers ----------------
__device__ __forceinline__ u32 smem_u32(const void* p) {
    u32 a;
    asm("{ .reg .u64 t; cvta.to.shared.u64 t, %1; cvt.u32.u64 %0, t; }" : "=r"(a) : "l"(p));
    return a;
}
__device__ __forceinline__ void ldsm4(u32 a, u32* r) {
    asm volatile("ldmatrix.sync.aligned.m8n8.x4.shared.b16 {%0,%1,%2,%3}, [%4];"
        : "=r"(r[0]), "=r"(r[1]), "=r"(r[2]), "=r"(r[3]) : "r"(a));
}
__device__ __forceinline__ void mmabf(float* d, const u32* a, u32 b0, u32 b1) {
    asm volatile("mma.sync.aligned.m16n8k16.row.col.f32.bf16.bf16.f32 "
        "{%0,%1,%2,%3},{%4,%5,%6,%7},{%8,%9},{%0,%1,%2,%3};"
        : "+f"(d[0]), "+f"(d[1]), "+f"(d[2]), "+f"(d[3])
        : "r"(a[0]), "r"(a[1]), "r"(a[2]), "r"(a[3]), "r"(b0), "r"(b1));
}

// split 8 fp32 into bf16 hi + bf16 lo, store 16B at swizzled slot of K-minor tile
__device__ __forceinline__ void split8(char* hi, char* lo, int r, int slot,
                                       const float* f)
{
    u32 H[4], L[4];
#pragma unroll
    for (int j = 0; j < 4; j++) {
        float a = f[2 * j], b = f[2 * j + 1];
        __nv_bfloat16 ha = __float2bfloat16(a), hb = __float2bfloat16(b);
        float fa = __bfloat162float(ha), fb = __bfloat162float(hb);
        __nv_bfloat162 hp; hp.x = ha; hp.y = hb;
        H[j] = *(u32*)&hp;
        __nv_bfloat162 lp = __floats2bfloat162_rn(a - fa, b - fb);
        L[j] = *(u32*)&lp;
    }
    u32 off = (u32)r * 256 + (u32)((slot ^ (r & 7)) << 4);
    *(uint4*)(hi + off) = make_uint4(H[0], H[1], H[2], H[3]);
    *(uint4*)(lo + off) = make_uint4(L[0], L[1], L[2], L[3]);
}

// 128x128x128 warp-tile GEMM (accumulating): D[m][n] += A[m][k]*B[n][k]
__device__ __forceinline__ void warp_gemm128(u32 ah, u32 al, u32 bh, u32 bl,
                                             int lane, int m0, int n0,
                                             float acc[2][4][4])
{
    int rA = lane & 15, hi16 = lane >> 4;
    int rBl = (lane & 7) + ((lane >> 4) << 3);
    int kh = (lane >> 3) & 1;
    int rowA[2] = {m0 + rA, m0 + 16 + rA};
    int rowB[2] = {n0 + rBl, n0 + 16 + rBl};
#pragma unroll
    for (int ks = 0; ks < 8; ks++) {
        u32 AH[2][4], AL[2][4], BH[2][4], BL[2][4];
#pragma unroll
        for (int f = 0; f < 2; f++) {
            u32 sa = (u32)rowA[f] * 256 + (u32)((((ks << 1) + hi16) ^ (rowA[f] & 7)) << 4);
            ldsm4(ah + sa, AH[f]);
            ldsm4(al + sa, AL[f]);
            u32 sb = (u32)rowB[f] * 256 + (u32)((((ks << 1) + kh) ^ (rowB[f] & 7)) << 4);
            ldsm4(bh + sb, BH[f]);
            ldsm4(bl + sb, BL[f]);
        }
#pragma unroll
        for (int mf = 0; mf < 2; mf++)
#pragma unroll
            for (int nh = 0; nh < 2; nh++)
#pragma unroll
                for (int no = 0; no < 2; no++) {
                    float* d = acc[mf][nh * 2 + no];
                    mmabf(d, AH[mf], BH[nh][2 * no], BH[nh][2 * no + 1]);
                    mmabf(d, AH[mf], BL[nh][2 * no], BL[nh][2 * no + 1]);
                    mmabf(d, AL[mf], BH[nh][2 * no], BH[nh][2 * no + 1]);
                }
    }
}

// f32 staging swizzle: value (row, col) at row*128 + ((col ^ row) & 127)
__device__ __forceinline__ int stg_i(int row, int col) {
    return row * 128 + ((col ^ row) & 127);
}

// ---------------- K1: transpose-in-smem + S GEMM + fused softmax stats ------
// smem: Ahi 0, Alo 32768, Bhi 65536, Blo 98304, Stg 131072(64KB),
//       s0s 196608, s1s 197120, qms 197632, cms 198144, red1 198656, red2 200704
#define K1_SMEM 202752

__global__ __launch_bounds__(512) void k1_score(
    const float* __restrict__ c_g, const float* __restrict__ q_g,
    const float* __restrict__ cmask, const float* __restrict__ qmask,
    const float* __restrict__ wc, const float* __restrict__ wq,
    const float* __restrict__ wcq, const float* __restrict__ bias)
{
    extern __shared__ __align__(256) char smem[];
    u32 sb = smem_u32(smem);
    float* Stg  = (float*)(smem + 131072);
    float* s0s  = (float*)(smem + 196608);
    float* s1s  = (float*)(smem + 197120);
    float* qms  = (float*)(smem + 197632);
    float* cms  = (float*)(smem + 198144);
    float* red1 = (float*)(smem + 198656);   // [4][128]
    float* red2 = (float*)(smem + 200704);   // [4][128]
    int tid = threadIdx.x, lane = tid & 31, wid = tid >> 5;
    int b = blockIdx.y, ct = blockIdx.x, c0 = ct * 128;
    float biasv = bias[0];

    // ---- phase A: stage c tile transposed: Stg[cc][h] ----
    for (int i = tid; i < 2048; i += 512) {
        int h = i >> 4, sx = i & 15;
        const float* p = &c_g[((size_t)b * Hn + h) * Cn + c0 + sx * 8];
        float4 v0 = *(const float4*)p, v1 = *(const float4*)(p + 4);
        float f[8] = {v0.x, v0.y, v0.z, v0.w, v1.x, v1.y, v1.z, v1.w};
#pragma unroll
        for (int j = 0; j < 8; j++) Stg[stg_i(sx * 8 + j, h)] = f[j];
    }
    __syncthreads();
    // ---- phase A2: split to A tiles + s0 ----
    for (int i = tid; i < 2048; i += 512) {
        int cc = i >> 4, hs = i & 15, h0 = hs * 8;
        float f[8];
#pragma unroll
        for (int j = 0; j < 8; j++) f[j] = Stg[stg_i(cc, h0 + j)];
        split8(smem, smem + 32768, cc, hs, f);
        float p = 0.f;
#pragma unroll
        for (int j = 0; j < 8; j++) p += f[j] * wc[h0 + j];
        p += __shfl_xor_sync(~0u, p, 1);
        p += __shfl_xor_sync(~0u, p, 2);
        p += __shfl_xor_sync(~0u, p, 4);
        p += __shfl_xor_sync(~0u, p, 8);
        if ((lane & 15) == 0) s0s[cc] = p + biasv;
    }
    __syncthreads();
    // ---- phase B: stage q tile transposed ----
    for (int i = tid; i < 2048; i += 512) {
        int h = i >> 4, sx = i & 15;
        const float* p = &q_g[((size_t)b * Hn + h) * Qn + sx * 8];
        float4 v0 = *(const float4*)p, v1 = *(const float4*)(p + 4);
        float f[8] = {v0.x, v0.y, v0.z, v0.w, v1.x, v1.y, v1.z, v1.w};
#pragma unroll
        for (int j = 0; j < 8; j++) Stg[stg_i(sx * 8 + j, h)] = f[j];
    }
    __syncthreads();
    // ---- phase B2: split to B tiles (scaled by wcq) + s1 ----
    for (int i = tid; i < 2048; i += 512) {
        int qq = i >> 4, hs = i & 15, h0 = hs * 8;
        float f[8];
#pragma unroll
        for (int j = 0; j < 8; j++) f[j] = Stg[stg_i(qq, h0 + j)];
        float p = 0.f;
#pragma unroll
        for (int j = 0; j < 8; j++) p += f[j] * wq[h0 + j];
        p += __shfl_xor_sync(~0u, p, 1);
        p += __shfl_xor_sync(~0u, p, 2);
        p += __shfl_xor_sync(~0u, p, 4);
        p += __shfl_xor_sync(~0u, p, 8);
        if ((lane & 15) == 0) s1s[qq] = p;
#pragma unroll
        for (int j = 0; j < 8; j++) f[j] *= wcq[h0 + j];
        split8(smem + 65536, smem + 98304, qq, hs, f);
    }
    if (tid < 128) qms[tid] = qmask[b * Qn + tid];
    else if (tid < 256) cms[tid - 128] = cmask[b * Cn + c0 + tid - 128];
    __syncthreads();

    float acc[2][4][4];
#pragma unroll
    for (int i = 0; i < 2; i++)
#pragma unroll
        for (int j = 0; j < 4; j++)
#pragma unroll
            for (int k = 0; k < 4; k++) acc[i][j][k] = 0.f;

    int m0 = (wid >> 2) * 32, n0 = (wid & 3) * 32;
    warp_gemm128(sb, sb + 32768, sb + 65536, sb + 98304, lane, m0, n0, acc);

    int lr = lane >> 2, lc2 = (lane & 3) * 2;

    // finalize S: acc += s0[row] + s1[col]
#pragma unroll
    for (int mf = 0; mf < 2; mf++) {
        int r0 = m0 + mf * 16 + lr, r1 = r0 + 8;
        float s0a = s0s[r0], s0b = s0s[r1];
#pragma unroll
        for (int nf = 0; nf < 4; nf++) {
            int col = n0 + nf * 8 + lc2;
            float s1a = s1s[col], s1b = s1s[col + 1];
            acc[mf][nf][0] += s0a + s1a;
            acc[mf][nf][1] += s0a + s1b;
            acc[mf][nf][2] += s0b + s1a;
            acc[mf][nf][3] += s0b + s1b;
        }
    }

    // write S [c][q]
#pragma unroll
    for (int mf = 0; mf < 2; mf++) {
        int r0 = m0 + mf * 16 + lr, r1 = r0 + 8;
#pragma unroll
        for (int nf = 0; nf < 4; nf++) {
            int col = n0 + nf * 8 + lc2;
            *(float2*)&g_S[((size_t)b * Cn + c0 + r0) * Qn + col] =
                make_float2(acc[mf][nf][0], acc[mf][nf][1]);
            *(float2*)&g_S[((size_t)b * Cn + c0 + r1) * Qn + col] =
                make_float2(acc[mf][nf][2], acc[mf][nf][3]);
        }
    }

    // masks
    bool qm0[4], qm1[4];
#pragma unroll
    for (int nf = 0; nf < 4; nf++) {
        qm0[nf] = qms[n0 + nf * 8 + lc2] > 0.f;
        qm1[nf] = qms[n0 + nf * 8 + lc2 + 1] > 0.f;
    }
    bool cmv[2][2];
#pragma unroll
    for (int mf = 0; mf < 2; mf++) {
        cmv[mf][0] = cms[m0 + mf * 16 + lr] > 0.f;
        cmv[mf][1] = cms[m0 + mf * 16 + 8 + lr] > 0.f;
    }

    // ---- row stats (softmax over q) ----
    float rmx[2][2];
#pragma unroll
    for (int mf = 0; mf < 2; mf++) { rmx[mf][0] = -1e30f; rmx[mf][1] = -1e30f; }
#pragma unroll
    for (int mf = 0; mf < 2; mf++)
#pragma unroll
        for (int nf = 0; nf < 4; nf++) {
            if (qm0[nf]) {
                rmx[mf][0] = fmaxf(rmx[mf][0], acc[mf][nf][0]);
                rmx[mf][1] = fmaxf(rmx[mf][1], acc[mf][nf][2]);
            }
            if (qm1[nf]) {
                rmx[mf][0] = fmaxf(rmx[mf][0], acc[mf][nf][1]);
                rmx[mf][1] = fmaxf(rmx[mf][1], acc[mf][nf][3]);
            }
        }
#pragma unroll
    for (int mf = 0; mf < 2; mf++)
#pragma unroll
        for (int h = 0; h < 2; h++) {
            rmx[mf][h] = fmaxf(rmx[mf][h], __shfl_xor_sync(~0u, rmx[mf][h], 1));
            rmx[mf][h] = fmaxf(rmx[mf][h], __shfl_xor_sync(~0u, rmx[mf][h], 2));
        }
    if ((lane & 3) == 0)
#pragma unroll
        for (int mf = 0; mf < 2; mf++)
#pragma unroll
            for (int h = 0; h < 2; h++)
                red1[(wid & 3) * 128 + m0 + mf * 16 + h * 8 + lr] = rmx[mf][h];
    __syncthreads();

    float rowMv[2][2];
#pragma unroll
    for (int mf = 0; mf < 2; mf++)
#pragma unroll
        for (int h = 0; h < 2; h++) {
            int r = m0 + mf * 16 + h * 8 + lr;
            float m = red1[r];
#pragma unroll
            for (int g = 1; g < 4; g++) m = fmaxf(m, red1[g * 128 + r]);
            rowMv[mf][h] = m;
        }
    float rzz[2][2] = {{0.f, 0.f}, {0.f, 0.f}};
#pragma unroll
    for (int mf = 0; mf < 2; mf++)
#pragma unroll
        for (int nf = 0; nf < 4; nf++) {
            if (qm0[nf]) {
                rzz[mf][0] += __expf(acc[mf][nf][0] - rowMv[mf][0]);
                rzz[mf][1] += __expf(acc[mf][nf][2] - rowMv[mf][1]);
            }
            if (qm1[nf]) {
                rzz[mf][0] += __expf(acc[mf][nf][1] - rowMv[mf][0]);
                rzz[mf][1] += __expf(acc[mf][nf][3] - rowMv[mf][1]);
            }
        }
#pragma unroll
    for (int mf = 0; mf < 2; mf++)
#pragma unroll
        for (int h = 0; h < 2; h++) {
            rzz[mf][h] += __shfl_xor_sync(~0u, rzz[mf][h], 1);
            rzz[mf][h] += __shfl_xor_sync(~0u, rzz[mf][h], 2);
        }
    if ((lane & 3) == 0)
#pragma unroll
        for (int mf = 0; mf < 2; mf++)
#pragma unroll
            for (int h = 0; h < 2; h++)
                red2[(wid & 3) * 128 + m0 + mf * 16 + h * 8 + lr] = rzz[mf][h];
    __syncthreads();

    if ((wid & 3) == 0 && (lane & 3) == 0) {
#pragma unroll
        for (int mf = 0; mf < 2; mf++)
#pragma unroll
            for (int h = 0; h < 2; h++) {
                int r = m0 + mf * 16 + h * 8 + lr;
                float z = red2[r] + red2[128 + r] + red2[256 + r] + red2[384 + r];
                g_rowM[b * Cn + c0 + r] = rowMv[mf][h];
                g_rowZ[b * Cn + c0 + r] = z;
            }
    }
    __syncthreads();

    // ---- column partial stats (softmax over c, this tile) ----
    float cmx[4][2];
#pragma unroll
    for (int nf = 0; nf < 4; nf++) { cmx[nf][0] = -1e30f; cmx[nf][1] = -1e30f; }
#pragma unroll
    for (int mf = 0; mf < 2; mf++)
#pragma unroll
        for (int nf = 0; nf < 4; nf++) {
            if (cmv[mf][0]) {
                cmx[nf][0] = fmaxf(cmx[nf][0], acc[mf][nf][0]);
                cmx[nf][1] = fmaxf(cmx[nf][1], acc[mf][nf][1]);
            }
            if (cmv[mf][1]) {
                cmx[nf][0] = fmaxf(cmx[nf][0], acc[mf][nf][2]);
                cmx[nf][1] = fmaxf(cmx[nf][1], acc[mf][nf][3]);
            }
        }
#pragma unroll
    for (int nf = 0; nf < 4; nf++)
#pragma unroll
        for (int v = 0; v < 2; v++) {
            cmx[nf][v] = fmaxf(cmx[nf][v], __shfl_xor_sync(~0u, cmx[nf][v], 4));
            cmx[nf][v] = fmaxf(cmx[nf][v], __shfl_xor_sync(~0u, cmx[nf][v], 8));
            cmx[nf][v] = fmaxf(cmx[nf][v], __shfl_xor_sync(~0u, cmx[nf][v], 16));
        }
    if (lr == 0)
#pragma unroll
        for (int nf = 0; nf < 4; nf++) {
            red1[(wid >> 2) * 128 + n0 + nf * 8 + lc2]     = cmx[nf][0];
            red1[(wid >> 2) * 128 + n0 + nf * 8 + lc2 + 1] = cmx[nf][1];
        }
    __syncthreads();

    float pMv[4][2];
#pragma unroll
    for (int nf = 0; nf < 4; nf++)
#pragma unroll
        for (int v = 0; v < 2; v++) {
            int col = n0 + nf * 8 + lc2 + v;
            float m = red1[col];
#pragma unroll
            for (int g = 1; g < 4; g++) m = fmaxf(m, red1[g * 128 + col]);
            pMv[nf][v] = m;
        }
    float czz[4][2] = {{0,0},{0,0},{0,0},{0,0}};
#pragma unroll
    for (int mf = 0; mf < 2; mf++)
#pragma unroll
        for (int nf = 0; nf < 4; nf++) {
            if (cmv[mf][0]) {
                czz[nf][0] += __expf(acc[mf][nf][0] - pMv[nf][0]);
                czz[nf][1] += __expf(acc[mf][nf][1] - pMv[nf][1]);
            }
            if (cmv[mf][1]) {
                czz[nf][0] += __expf(acc[mf][nf][2] - pMv[nf][0]);
                czz[nf][1] += __expf(acc[mf][nf][3] - pMv[nf][1]);
            }
        }
#pragma unroll
    for (int nf = 0; nf < 4; nf++)
#pragma unroll
        for (int v = 0; v < 2; v++) {
            czz[nf][v] += __shfl_xor_sync(~0u, czz[nf][v], 4);
            czz[nf][v] += __shfl_xor_sync(~0u, czz[nf][v], 8);
            czz[nf][v] += __shfl_xor_sync(~0u, czz[nf][v], 16);
        }
    if (lr == 0)
#pragma unroll
        for (int nf = 0; nf < 4; nf++) {
            red2[(wid >> 2) * 128 + n0 + nf * 8 + lc2]     = czz[nf][0];
            red2[(wid >> 2) * 128 + n0 + nf * 8 + lc2 + 1] = czz[nf][1];
        }
    __syncthreads();

    if ((wid >> 2) == 0 && lr == 0) {
#pragma unroll
        for (int nf = 0; nf < 4; nf++)
#pragma unroll
            for (int v = 0; v < 2; v++) {
                int col = n0 + nf * 8 + lc2 + v;
                float z = red2[col] + red2[128 + col] + red2[256 + col] + red2[384 + col];
                g_pM[(b * NT + ct) * Qn + col] = pMv[nf][v];
                g_pZ[(b * NT + ct) * Qn + col] = z;
            }
    }
}

// ---------------- K3: qb^T partials = c · E2^T, split-K over 2 halves --------
// smem: Ahi 0, Alo 32768, Ehi 65536, Elo 98304, Stg 131072(64KB), colMs 196608
#define K3_SMEM 197120

__global__ __launch_bounds__(512) void k3_qb(
    const float* __restrict__ c_g, const float* __restrict__ cmask)
{
    extern __shared__ __align__(256) char smem[];
    u32 sb = smem_u32(smem);
    float* Stg   = (float*)(smem + 131072);
    float* colMs = (float*)(smem + 196608);
    int tid = threadIdx.x, lane = tid & 31, wid = tid >> 5;
    int b = blockIdx.y, half = blockIdx.x;

    if (tid < 128) {
        float m = -3.4e38f;
#pragma unroll
        for (int t = 0; t < NT; t++) m = fmaxf(m, g_pM[(b * NT + t) * Qn + tid]);
        colMs[tid] = m;
    }

    float acc[2][4][4];
#pragma unroll
    for (int i = 0; i < 2; i++)
#pragma unroll
        for (int j = 0; j < 4; j++)
#pragma unroll
            for (int k = 0; k < 4; k++) acc[i][j][k] = 0.f;

    int m0 = (wid >> 2) * 32, n0 = (wid & 3) * 32;

    for (int t = 0; t < 4; t++) {
        int c0 = (half * 4 + t) * 128;
        __syncthreads();    // protects tiles/Stg from previous iter, colMs on t=0
        // A fill: c rows (M=h, K=c-minor, natural layout)
        for (int i = tid; i < 2048; i += 512) {
            int r = i >> 4, sx = i & 15;
            const float* pa = &c_g[((size_t)b * Hn + r) * Cn + c0 + sx * 8];
            float4 v0 = *(const float4*)pa, v1 = *(const float4*)(pa + 4);
            float f[8] = {v0.x, v0.y, v0.z, v0.w, v1.x, v1.y, v1.z, v1.w};
            split8(smem, smem + 32768, r, sx, f);
        }
        // stage E transposed: read S [c-rows][q], write Stg[q][c] with exp+mask
        for (int i = tid; i < 2048; i += 512) {
            int r = i >> 4, sx = i & 15;
            const float* ps = &g_S[((size_t)b * Cn + c0 + r) * Qn + sx * 8];
            float4 s0 = *(const float4*)ps, s1 = *(const float4*)(ps + 4);
            float f[8] = {s0.x, s0.y, s0.z, s0.w, s1.x, s1.y, s1.z, s1.w};
            bool cmv = cmask[b * Cn + c0 + r] > 0.f;
#pragma unroll
            for (int j = 0; j < 8; j++) {
                int q = sx * 8 + j;
                Stg[stg_i(q, r)] = cmv ? __expf(f[j] - colMs[q]) : 0.f;
            }
        }
        __syncthreads();
        // split E tiles [q][c-minor]
        for (int i = tid; i < 2048; i += 512) {
            int qq = i >> 4, cs = i & 15, cb0 = cs * 8;
            float f[8];
#pragma unroll
            for (int j = 0; j < 8; j++) f[j] = Stg[stg_i(qq, cb0 + j)];
            split8(smem + 65536, smem + 98304, qq, cs, f);
        }
        __syncthreads();
        warp_gemm128(sb, sb + 32768, sb + 65536, sb + 98304, lane, m0, n0, acc);
    }

    int lr = lane >> 2, lc2 = (lane & 3) * 2;
#pragma unroll
    for (int mf = 0; mf < 2; mf++) {
        int h0 = m0 + mf * 16 + lr, h1 = h0 + 8;
#pragma unroll
        for (int nf = 0; nf < 4; nf++) {
            int col = n0 + nf * 8 + lc2;
            *(float2*)&g_qbp2[((size_t)(b * 2 + half) * Hn + h0) * Qn + col] =
                make_float2(acc[mf][nf][0], acc[mf][nf][1]);
            *(float2*)&g_qbp2[((size_t)(b * 2 + half) * Hn + h1) * Qn + col] =
                make_float2(acc[mf][nf][2], acc[mf][nf][3]);
        }
    }
}

// ---------------- K4: a = E·q^T, bb = E·qb^T; assemble output ----------------
// smem: Ehi 0, Elo 32768, Qhi 65536, Qlo 98304, Phi 131072, Plo 163840,
//       rms 196608, qms 197120, rzs 197632, rcz 198144
#define K4_SMEM 198656

__global__ __launch_bounds__(512) void k4_out(
    const float* __restrict__ c_g, const float* __restrict__ q_g,
    const float* __restrict__ qmask, float* __restrict__ out)
{
    extern __shared__ __align__(256) char smem[];
    u32 sb = smem_u32(smem);
    float* rms = (float*)(smem + 196608);
    float* qms = (float*)(smem + 197120);
    float* rzs = (float*)(smem + 197632);
    float* rcz = (float*)(smem + 198144);
    int tid = threadIdx.x, lane = tid & 31, wid = tid >> 5;
    int b = blockIdx.y, ct = blockIdx.x, c0 = ct * 128;

    if (tid < 128) rms[tid] = g_rowM[b * Cn + c0 + tid];
    else if (tid < 256) qms[tid - 128] = qmask[b * Qn + tid - 128];
    else if (tid < 384) {
        float z = g_rowZ[b * Cn + c0 + tid - 256];
        rzs[tid - 256] = (z > 0.f) ? 1.f / z : 0.f;
    } else {
        int qq = tid - 384;
        float m = -3.4e38f;
#pragma unroll
        for (int t = 0; t < NT; t++) m = fmaxf(m, g_pM[(b * NT + t) * Qn + qq]);
        float z = 0.f;
#pragma unroll
        for (int t = 0; t < NT; t++)
            z += g_pZ[(b * NT + t) * Qn + qq] * __expf(g_pM[(b * NT + t) * Qn + qq] - m);
        rcz[qq] = (z > 0.f) ? 1.f / z : 0.f;
    }
    __syncthreads();

    for (int i = tid; i < 2048; i += 512) {
        int r = i >> 4, sx = i & 15;
        const float* ps = &g_S[((size_t)b * Cn + c0 + r) * Qn + sx * 8];
        float4 s0 = *(const float4*)ps, s1 = *(const float4*)(ps + 4);
        float fe[8] = {s0.x, s0.y, s0.z, s0.w, s1.x, s1.y, s1.z, s1.w};
        float rm = rms[r];
#pragma unroll
        for (int j = 0; j < 8; j++)
            fe[j] = (qms[sx * 8 + j] > 0.f) ? __expf(fe[j] - rm) : 0.f;
        split8(smem, smem + 32768, r, sx, fe);
        const float* pq = &q_g[((size_t)b * Hn + r) * Qn + sx * 8];
        float4 q0 = *(const float4*)pq, q1 = *(const float4*)(pq + 4);
        float fq[8] = {q0.x, q0.y, q0.z, q0.w, q1.x, q1.y, q1.z, q1.w};
        split8(smem + 65536, smem + 98304, r, sx, fq);
        const float* p0 = &g_qbp2[((size_t)(b * 2) * Hn + r) * Qn + sx * 8];
        const float* p1 = p0 + (size_t)Hn * Qn;
        float4 a0 = *(const float4*)p0, a1 = *(const float4*)(p0 + 4);
        float4 b0 = *(const float4*)p1, b1 = *(const float4*)(p1 + 4);
        float fp[8] = {a0.x + b0.x, a0.y + b0.y, a0.z + b0.z, a0.w + b0.w,
                       a1.x + b1.x, a1.y + b1.y, a1.z + b1.z, a1.w + b1.w};
#pragma unroll
        for (int j = 0; j < 8; j++) fp[j] *= rcz[sx * 8 + j];
        split8(smem + 131072, smem + 163840, r, sx, fp);
    }
    __syncthreads();

    int m0 = (wid >> 2) * 32, n0 = (wid & 3) * 32;
    int lr = lane >> 2, lc = (lane & 3) * 2;

    {
        float acc[2][4][4];
#pragma unroll
        for (int i = 0; i < 2; i++)
#pragma unroll
            for (int j = 0; j < 4; j++)
#pragma unroll
                for (int k = 0; k < 4; k++) acc[i][j][k] = 0.f;
        warp_gemm128(sb, sb + 32768, sb + 65536, sb + 98304, lane, m0, n0, acc);
        __syncthreads();
        float* StA = (float*)(smem + 65536);
#pragma unroll
        for (int mf = 0; mf < 2; mf++) {
            int cl0 = m0 + mf * 16 + lr, cl1 = cl0 + 8;
            float rz0 = rzs[cl0], rz1 = rzs[cl1];
#pragma unroll
            for (int nf = 0; nf < 4; nf++) {
                int h = n0 + nf * 8 + lc;
                StA[(h << 7) + ((cl0 ^ h) & 127)]             = acc[mf][nf][0] * rz0;
                StA[((h + 1) << 7) + ((cl0 ^ (h + 1)) & 127)] = acc[mf][nf][1] * rz0;
                StA[(h << 7) + ((cl1 ^ h) & 127)]             = acc[mf][nf][2] * rz1;
                StA[((h + 1) << 7) + ((cl1 ^ (h + 1)) & 127)] = acc[mf][nf][3] * rz1;
            }
        }
    }
    {
        float acc[2][4][4];
#pragma unroll
        for (int i = 0; i < 2; i++)
#pragma unroll
            for (int j = 0; j < 4; j++)
#pragma unroll
                for (int k = 0; k < 4; k++) acc[i][j][k] = 0.f;
        warp_gemm128(sb, sb + 32768, sb + 131072, sb + 163840, lane, m0, n0, acc);
        __syncthreads();
        float* StB = (float*)smem;
#pragma unroll
        for (int mf = 0; mf < 2; mf++) {
            int cl0 = m0 + mf * 16 + lr, cl1 = cl0 + 8;
            float rz0 = rzs[cl0], rz1 = rzs[cl1];
#pragma unroll
            for (int nf = 0; nf < 4; nf++) {
                int h = n0 + nf * 8 + lc;
                StB[(h << 7) + ((cl0 ^ h) & 127)]             = acc[mf][nf][0] * rz0;
                StB[((h + 1) << 7) + ((cl0 ^ (h + 1)) & 127)] = acc[mf][nf][1] * rz0;
                StB[(h << 7) + ((cl1 ^ h) & 127)]             = acc[mf][nf][2] * rz1;
                StB[((h + 1) << 7) + ((cl1 ^ (h + 1)) & 127)] = acc[mf][nf][3] * rz1;
            }
        }
    }
    __syncthreads();

    float* StA = (float*)(smem + 65536);
    float* StB = (float*)smem;
    const size_t HC = (size_t)Hn * Cn;
    for (int i = tid; i < 16384; i += 512) {
        int h = i >> 7, cc = i & 127;
        float a  = StA[(h << 7) + ((cc ^ h) & 127)];
        float bb = StB[(h << 7) + ((cc ^ h) & 127)];
        float cv = c_g[((size_t)b * Hn + h) * Cn + c0 + cc];
        size_t o = (size_t)b * 4 * HC + (size_t)h * Cn + c0 + cc;
        out[o]          = cv;
        out[o + HC]     = a;
        out[o + 2 * HC] = cv * a;
        out[o + 3 * HC] = cv * bb;
    }
}

// ---------------- launch ----------------
extern "C" void kernel_launch(void* const* d_in, const int* in_sizes, int n_in,
                              void* d_out, int out_size)
{
    const float* c     = (const float*)d_in[0];
    const float* q     = (const float*)d_in[1];
    const float* cmask = (const float*)d_in[2];
    const float* qmask = (const float*)d_in[3];
    const float* wc    = (const float*)d_in[4];
    const float* wq    = (const float*)d_in[5];
    const float* wcq   = (const float*)d_in[6];
    const float* bias  = (const float*)d_in[7];
    float* out = (float*)d_out;

    cudaFuncSetAttribute(k1_score, cudaFuncAttributeMaxDynamicSharedMemorySize, K1_SMEM);
    cudaFuncSetAttribute(k3_qb,    cudaFuncAttributeMaxDynamicSharedMemorySize, K3_SMEM);
    cudaFuncSetAttribute(k4_out,   cudaFuncAttributeMaxDynamicSharedMemorySize, K4_SMEM);

    k1_score<<<dim3(NT, Bn), 512, K1_SMEM>>>(c, q, cmask, qmask, wc, wq, wcq, bias);
    k3_qb<<<dim3(2, Bn), 512, K3_SMEM>>>(c, cmask);
    k4_out<<<dim3(NT, Bn), 512, K4_SMEM>>>(c, q, qmask, out);
}